// round 8
// baseline (speedup 1.0000x reference)
#include <cuda_runtime.h>
#include <math_constants.h>
#include <cstdint>

// ---------------- scratch (static device globals; no allocation) ------------
__device__ float    d_dist[16 * 1024 * 1024];  // pairwise scores (64MB)
__device__ float    d_sq  [16 * 1024];
__device__ int      d_idx [16 * 1024 * 40];
__device__ float    d_pq  [16 * 1024 * 512];
__device__ float    d_cat [16 * 1024 * 512];
__device__ float    d_wpq [92160];
__device__ unsigned d_gmax[16 * 1024];
// tf32 hi/lo split buffers
__device__ uint32_t d_ahi[16 * 1024 * 128], d_alo[16 * 1024 * 128];  // cat slice
__device__ uint32_t d_whi[92160],           d_wlo[92160];            // wpq
__device__ uint32_t d_fhi[1024 * 512],      d_flo[1024 * 512];       // wf
__device__ uint32_t d_chi[16 * 1024 * 512], d_clo[16 * 1024 * 512];  // full cat

static __device__ __forceinline__ unsigned encf(float v) {
    unsigned u = __float_as_uint(v);
    return (u & 0x80000000u) ? ~u : (u | 0x80000000u);
}
static __device__ __forceinline__ void cvt_split(float v, uint32_t& h, uint32_t& l) {
    asm("cvt.rna.tf32.f32 %0, %1;" : "=r"(h) : "f"(v));
    float r = v - __uint_as_float(h);
    asm("cvt.rna.tf32.f32 %0, %1;" : "=r"(l) : "f"(r));
}
static __device__ __forceinline__ void mma_tf32(float* c, uint32_t a0, uint32_t a1,
                                                uint32_t a2, uint32_t a3,
                                                uint32_t b0, uint32_t b1) {
    asm volatile(
        "mma.sync.aligned.m16n8k8.row.col.f32.tf32.tf32.f32 "
        "{%0,%1,%2,%3}, {%4,%5,%6,%7}, {%8,%9}, {%0,%1,%2,%3};"
        : "+f"(c[0]), "+f"(c[1]), "+f"(c[2]), "+f"(c[3])
        : "r"(a0), "r"(a1), "r"(a2), "r"(a3), "r"(b0), "r"(b1));
}

static constexpr int HG_STRIDE = 24;
static constexpr int HG_ARR = 128 * HG_STRIDE;
static constexpr int HG_SMEM = 4 * HG_ARR * 4;   // 49152 bytes

static __device__ __forceinline__ int sidx(int k) {
    int ks = k >> 3, kk = k & 7;
    return ks * 8 + ((kk & 3) << 1) + (kk >> 2);
}

// ---------------- conversion kernels ----------------------------------------
__global__ void cvt1d(const float* __restrict__ src, uint32_t* __restrict__ hi,
                      uint32_t* __restrict__ lo, int n4)
{
    int i = blockIdx.x * 256 + threadIdx.x;
    if (i >= n4) return;
    float4 v = ((const float4*)src)[i];
    uint4 h, l;
    cvt_split(v.x, h.x, l.x);
    cvt_split(v.y, h.y, l.y);
    cvt_split(v.z, h.z, l.z);
    cvt_split(v.w, h.w, l.w);
    ((uint4*)hi)[i] = h;
    ((uint4*)lo)[i] = l;
}

__global__ void cvt2d(const float* __restrict__ src, int ld, int cols,
                      uint32_t* __restrict__ hi, uint32_t* __restrict__ lo)
{
    int i = blockIdx.x * 256 + threadIdx.x;       // over 16384*cols/4
    int c4s = cols >> 2;
    int r = i / c4s, c4 = i - r * c4s;
    if (r >= 16384) return;
    float4 v = *(const float4*)&src[(size_t)r * ld + c4 * 4];
    uint4 h, l;
    cvt_split(v.x, h.x, l.x);
    cvt_split(v.y, h.y, l.y);
    cvt_split(v.z, h.z, l.z);
    cvt_split(v.w, h.w, l.w);
    *(uint4*)&hi[(size_t)r * cols + c4 * 4] = h;
    *(uint4*)&lo[(size_t)r * cols + c4 * 4] = l;
}

// ============ generalized tf32x3 tensor GEMM: C = A(..xK) * B(NxK)^T ========
// mode 0: plain store.  mode 1: dist-symmetric (B=A, upper-tri, +mirror).
// mode 2: fused max over rows -> atomicMax(gmax).
__global__ void __launch_bounds__(256, 2)
tgemm(const uint32_t* __restrict__ Ahi, const uint32_t* __restrict__ Alo,
      int lda, long long sA,
      const uint32_t* __restrict__ Bhi, const uint32_t* __restrict__ Blo,
      int ldb,
      const float* __restrict__ sq,
      float* __restrict__ C, int ldc, long long sC,
      int N, int K, int mode, unsigned* __restrict__ gmax)
{
    extern __shared__ uint32_t dsm[];
    uint32_t* sAh = dsm;
    uint32_t* sAl = sAh + HG_ARR;
    uint32_t* sBh = sAl + HG_ARR;
    uint32_t* sBl = sBh + HG_ARR;

    int bz = blockIdx.z;
    Ahi += (long long)bz * sA;
    Alo += (long long)bz * sA;
    const float* sqb = sq ? sq + (long long)bz * 1024 : nullptr;
    C += (long long)bz * sC;

    int bi, bj;
    if (mode == 1) {
        int nb = N >> 7;
        int p = blockIdx.x;
        bi = 0;
        while (p >= nb - bi) { p -= nb - bi; bi++; }
        bj = bi + p;
    } else { bi = blockIdx.x; bj = blockIdx.y; }
    const int row0 = bi * 128, col0 = bj * 128;

    const uint32_t* Bh2 = (mode == 1) ? Ahi : Bhi;
    const uint32_t* Bl2 = (mode == 1) ? Alo : Blo;
    const int ldb2 = (mode == 1) ? lda : ldb;

    const int tid = threadIdx.x;
    const int wid = tid >> 5, lane = tid & 31;
    const int wr = wid >> 2, wc = wid & 3;
    const int g = lane >> 2, t = lane & 3;
    const int lrow = tid >> 2, lc4 = tid & 3;

    float acc[4][4][4];
#pragma unroll
    for (int mt = 0; mt < 4; mt++)
#pragma unroll
        for (int nt = 0; nt < 4; nt++)
#pragma unroll
            for (int i = 0; i < 4; i++) acc[mt][nt][i] = 0.f;

    const int nchunk = K >> 4;
    for (int ch = 0; ch < nchunk; ch++) {
        const int k0 = ch * 16;
        __syncthreads();
#pragma unroll
        for (int i = 0; i < 2; i++) {
            int row = i * 64 + lrow;
            uint4 vah = *(const uint4*)&Ahi[(size_t)(row0 + row) * lda + k0 + lc4 * 4];
            uint4 val = *(const uint4*)&Alo[(size_t)(row0 + row) * lda + k0 + lc4 * 4];
            uint4 vbh = *(const uint4*)&Bh2[(size_t)(col0 + row) * ldb2 + k0 + lc4 * 4];
            uint4 vbl = *(const uint4*)&Bl2[(size_t)(col0 + row) * ldb2 + k0 + lc4 * 4];
            uint32_t eah[4] = {vah.x, vah.y, vah.z, vah.w};
            uint32_t eal[4] = {val.x, val.y, val.z, val.w};
            uint32_t ebh[4] = {vbh.x, vbh.y, vbh.z, vbh.w};
            uint32_t ebl[4] = {vbl.x, vbl.y, vbl.z, vbl.w};
#pragma unroll
            for (int j = 0; j < 4; j++) {
                int s = sidx(lc4 * 4 + j);
                sAh[row * HG_STRIDE + s] = eah[j];
                sAl[row * HG_STRIDE + s] = eal[j];
                sBh[row * HG_STRIDE + s] = ebh[j];
                sBl[row * HG_STRIDE + s] = ebl[j];
            }
        }
        __syncthreads();

#pragma unroll
        for (int ks = 0; ks < 2; ks++) {
            uint2 bh[4], bl[4];
#pragma unroll
            for (int nt = 0; nt < 4; nt++) {
                int nb_ = wc * 32 + nt * 8 + g;
                bh[nt] = *(const uint2*)&sBh[nb_ * HG_STRIDE + ks * 8 + 2 * t];
                bl[nt] = *(const uint2*)&sBl[nb_ * HG_STRIDE + ks * 8 + 2 * t];
            }
            uint32_t af[4][4];
#pragma unroll
            for (int mt = 0; mt < 4; mt++) {
                int rb = wr * 64 + mt * 16 + g;
                uint2 a02 = *(const uint2*)&sAh[rb * HG_STRIDE + ks * 8 + 2 * t];
                uint2 a13 = *(const uint2*)&sAh[(rb + 8) * HG_STRIDE + ks * 8 + 2 * t];
                af[mt][0] = a02.x; af[mt][1] = a13.x;
                af[mt][2] = a02.y; af[mt][3] = a13.y;
            }
            // pass 1: Ah*Bh ; pass 2: Ah*Bl (af reused)
#pragma unroll
            for (int nt = 0; nt < 4; nt++)
#pragma unroll
                for (int mt = 0; mt < 4; mt++) {
                    mma_tf32(acc[mt][nt], af[mt][0], af[mt][1], af[mt][2],
                             af[mt][3], bh[nt].x, bh[nt].y);
                    mma_tf32(acc[mt][nt], af[mt][0], af[mt][1], af[mt][2],
                             af[mt][3], bl[nt].x, bl[nt].y);
                }
            // pass 3: Al*Bh
#pragma unroll
            for (int mt = 0; mt < 4; mt++) {
                int rb = wr * 64 + mt * 16 + g;
                uint2 a02 = *(const uint2*)&sAl[rb * HG_STRIDE + ks * 8 + 2 * t];
                uint2 a13 = *(const uint2*)&sAl[(rb + 8) * HG_STRIDE + ks * 8 + 2 * t];
                af[mt][0] = a02.x; af[mt][1] = a13.x;
                af[mt][2] = a02.y; af[mt][3] = a13.y;
            }
#pragma unroll
            for (int nt = 0; nt < 4; nt++)
#pragma unroll
                for (int mt = 0; mt < 4; mt++)
                    mma_tf32(acc[mt][nt], af[mt][0], af[mt][1], af[mt][2],
                             af[mt][3], bh[nt].x, bh[nt].y);
        }
    }

    if (mode == 2) {
        const int batch = row0 >> 10;
#pragma unroll
        for (int nt = 0; nt < 4; nt++)
#pragma unroll
            for (int j = 0; j < 2; j++) {
                float v = -CUDART_INF_F;
#pragma unroll
                for (int mt = 0; mt < 4; mt++)
                    v = fmaxf(v, fmaxf(acc[mt][nt][j], acc[mt][nt][j + 2]));
#pragma unroll
                for (int off = 4; off < 32; off <<= 1)
                    v = fmaxf(v, __shfl_xor_sync(0xffffffffu, v, off));
                if (lane < 4) {
                    int col = col0 + wc * 32 + nt * 8 + 2 * lane + j;
                    atomicMax(&gmax[batch * 1024 + col], encf(v));
                }
            }
        return;
    }

#pragma unroll
    for (int mt = 0; mt < 4; mt++)
#pragma unroll
        for (int nt = 0; nt < 4; nt++) {
            int r = row0 + wr * 64 + mt * 16 + g;
            int c = col0 + wc * 32 + nt * 8 + 2 * t;
            float v0 = acc[mt][nt][0], v1 = acc[mt][nt][1];
            float v2 = acc[mt][nt][2], v3 = acc[mt][nt][3];
            if (mode == 1) {
                float sr0 = sqb[r & 1023], sr8 = sqb[(r + 8) & 1023];
                float sc0 = sqb[c & 1023], sc1 = sqb[(c + 1) & 1023];
                v0 = 2.f * v0 - sr0 - sc0; v1 = 2.f * v1 - sr0 - sc1;
                v2 = 2.f * v2 - sr8 - sc0; v3 = 2.f * v3 - sr8 - sc1;
            }
            *(float2*)&C[(size_t)r * ldc + c] = make_float2(v0, v1);
            *(float2*)&C[(size_t)(r + 8) * ldc + c] = make_float2(v2, v3);
            if (mode == 1 && bi != bj) {
                C[(size_t)c * ldc + r] = v0;
                C[(size_t)(c + 1) * ldc + r] = v1;
                C[(size_t)c * ldc + r + 8] = v2;
                C[(size_t)(c + 1) * ldc + r + 8] = v3;
            }
        }
}

// ---------------- 128x128x8 FFMA SGEMM (layer 0 only, lda=3) ---------------
__global__ void __launch_bounds__(256, 2)
sgemm128(const float* __restrict__ A, int lda, long long sA,
         const float* __restrict__ B, int ldb, long long sB,
         const float* __restrict__ sq,
         float* __restrict__ C, int ldc, long long sC,
         int M, int N, int K, int mode)
{
    int bz = blockIdx.z;
    A += (long long)bz * sA;
    B += (long long)bz * sB;
    C += (long long)bz * sC;
    const float* sqb = sq ? (sq + (long long)bz * M) : nullptr;

    int bi, bj;
    if (mode == 1) {
        int nb = N >> 7;
        int p = blockIdx.x;
        bi = 0;
        while (p >= nb - bi) { p -= nb - bi; bi++; }
        bj = bi + p;
    } else { bi = blockIdx.x; bj = blockIdx.y; }
    const int row0 = bi * 128;
    const int col0 = bj * 128;

    __shared__ float As[2][8][132];
    __shared__ float Bs[2][8][132];

    const int tid = threadIdx.x;
    const int lk = tid & 7;
    const int lm = tid >> 3;
    const int tx = tid & 15;
    const int ty = tid >> 4;

    float acc[8][8];
#pragma unroll
    for (int i = 0; i < 8; i++)
#pragma unroll
        for (int j = 0; j < 8; j++) acc[i][j] = 0.f;

    float pa[4], pb[4];
    const int nk = (K + 7) >> 3;

    {
        int k = lk;
        bool ok = (k < K);
#pragma unroll
        for (int j = 0; j < 4; j++) {
            int m = lm + 32 * j;
            pa[j] = ok ? A[(long long)(row0 + m) * lda + k] : 0.f;
            pb[j] = ok ? B[(long long)(col0 + m) * ldb + k] : 0.f;
        }
#pragma unroll
        for (int j = 0; j < 4; j++) {
            As[0][lk][lm + 32 * j] = pa[j];
            Bs[0][lk][lm + 32 * j] = pb[j];
        }
    }
    __syncthreads();

    for (int t = 0; t < nk; t++) {
        int cur = t & 1;
        if (t + 1 < nk) {
            int k = (t + 1) * 8 + lk;
            bool ok = (k < K);
#pragma unroll
            for (int j = 0; j < 4; j++) {
                int m = lm + 32 * j;
                pa[j] = ok ? A[(long long)(row0 + m) * lda + k] : 0.f;
                pb[j] = ok ? B[(long long)(col0 + m) * ldb + k] : 0.f;
            }
        }
#pragma unroll
        for (int kk = 0; kk < 8; kk++) {
            float a[8], b[8];
            *(float4*)&a[0] = *(const float4*)&As[cur][kk][ty * 4];
            *(float4*)&a[4] = *(const float4*)&As[cur][kk][64 + ty * 4];
            *(float4*)&b[0] = *(const float4*)&Bs[cur][kk][tx * 4];
            *(float4*)&b[4] = *(const float4*)&Bs[cur][kk][64 + tx * 4];
#pragma unroll
            for (int i = 0; i < 8; i++)
#pragma unroll
                for (int j = 0; j < 8; j++)
                    acc[i][j] += a[i] * b[j];
        }
        if (t + 1 < nk) {
            int nxt = cur ^ 1;
#pragma unroll
            for (int j = 0; j < 4; j++) {
                As[nxt][lk][lm + 32 * j] = pa[j];
                Bs[nxt][lk][lm + 32 * j] = pb[j];
            }
        }
        __syncthreads();
    }

#pragma unroll
    for (int ih = 0; ih < 2; ih++) {
#pragma unroll
        for (int i = 0; i < 4; i++) {
            int r = row0 + ih * 64 + ty * 4 + i;
            float srow = (mode == 1) ? sqb[r] : 0.f;
#pragma unroll
            for (int jh = 0; jh < 2; jh++) {
                float outv[4];
#pragma unroll
                for (int j = 0; j < 4; j++) {
                    float v = acc[ih * 4 + i][jh * 4 + j];
                    if (mode == 1)
                        v = (2.f * v - srow) - sqb[col0 + jh * 64 + tx * 4 + j];
                    outv[j] = v;
                }
                *(float4*)&C[(long long)r * ldc + col0 + jh * 64 + tx * 4] =
                    *(float4*)&outv[0];
            }
        }
    }

    if (mode == 1 && bi != bj) {
#pragma unroll
        for (int jh = 0; jh < 2; jh++)
#pragma unroll
            for (int j = 0; j < 4; j++) {
                int c = col0 + jh * 64 + tx * 4 + j;
                float sc = sqb[c];
#pragma unroll
                for (int ih = 0; ih < 2; ih++) {
                    int rb = row0 + ih * 64 + ty * 4;
                    float mv[4];
#pragma unroll
                    for (int i = 0; i < 4; i++)
                        mv[i] = (2.f * acc[ih * 4 + i][jh * 4 + j] - sqb[rb + i]) - sc;
                    *(float4*)&C[(long long)c * ldc + rb] = *(float4*)&mv[0];
                }
            }
    }
}

// ---------------- squared norms ---------------------------------------------
__global__ void sq_kernel(const float* __restrict__ H, int lda, int C,
                          float* __restrict__ SQ)
{
    int gwarp = (blockIdx.x * blockDim.x + threadIdx.x) >> 5;
    int lane = threadIdx.x & 31;
    if (gwarp >= 16 * 1024) return;
    const float* h = H + (long long)gwarp * lda;
    float s = 0.f;
    for (int c = lane; c < C; c += 32) { float v = h[c]; s += v * v; }
#pragma unroll
    for (int d = 16; d > 0; d >>= 1) s += __shfl_down_sync(0xffffffffu, s, d);
    if (lane == 0) SQ[gwarp] = s;
}

// ---------------- top-40: per-warp iterative argmax + 8-way merge ----------
__global__ void topk40_kernel(const float* __restrict__ S, int* __restrict__ IDX)
{
    int row = blockIdx.x;
    const float* s = S + (long long)row * 1024;
    int tid = threadIdx.x;
    int lane = tid & 31, w = tid >> 5;

    unsigned key[4];
#pragma unroll
    for (int j = 0; j < 4; j++) {
        int m = w * 128 + j * 32 + lane;
        key[j] = encf(s[m]);
    }

    __shared__ unsigned long long lists[8][40];

    for (int it = 0; it < 40; it++) {
        unsigned loc = max(max(key[0], key[1]), max(key[2], key[3]));
        unsigned best = __reduce_max_sync(0xffffffffu, loc);
        unsigned b0 = __ballot_sync(0xffffffffu, key[0] == best);
        unsigned b1 = __ballot_sync(0xffffffffu, key[1] == best);
        unsigned b2 = __ballot_sync(0xffffffffu, key[2] == best);
        unsigned b3 = __ballot_sync(0xffffffffu, key[3] == best);
        int j; unsigned bb;
        if (b0)      { j = 0; bb = b0; }
        else if (b1) { j = 1; bb = b1; }
        else if (b2) { j = 2; bb = b2; }
        else         { j = 3; bb = b3; }
        int wlane = __ffs(bb) - 1;
        int m = w * 128 + j * 32 + wlane;
        if (lane == wlane) {
#pragma unroll
            for (int jj = 0; jj < 4; jj++) if (jj == j) key[jj] = 0u;
        }
        if (lane == 0)
            lists[w][it] = ((unsigned long long)best << 32) | (unsigned)(2047 - m);
    }
    __syncthreads();

    if (tid == 0) {
        unsigned long long head[8];
        int pos[8];
#pragma unroll
        for (int q = 0; q < 8; q++) { head[q] = lists[q][0]; pos[q] = 0; }
        for (int it = 0; it < 40; it++) {
            unsigned long long best = head[0];
#pragma unroll
            for (int q = 1; q < 8; q++) if (head[q] > best) best = head[q];
            IDX[row * 40 + it] = 2047 - (int)(best & 0xFFFFFFFFull);
#pragma unroll
            for (int q = 0; q < 8; q++)
                if (head[q] == best) {
                    pos[q]++;
                    head[q] = (pos[q] < 40) ? lists[q][pos[q]] : 0ull;
                }
        }
    }
}

// ---------------- weight transform ------------------------------------------
__global__ void wprep_kernel(const float* __restrict__ W, float* __restrict__ WPQ,
                             int Co, int C)
{
    int i = blockIdx.x * blockDim.x + threadIdx.x;
    if (i >= Co * C) return;
    int o = i / C, c = i % C;
    float wl = W[o * 2 * C + c];
    float wr = W[o * 2 * C + C + c];
    WPQ[o * C + c] = wl;
    WPQ[(Co + o) * C + c] = wr - wl;
}

// ---------------- gather-max + BN affine + LeakyReLU ------------------------
__global__ void edge_gathermax(const float* __restrict__ PQ,
                               const int* __restrict__ IDX,
                               const float* __restrict__ g,
                               const float* __restrict__ bb,
                               float* __restrict__ OUT,
                               int Co, int ldo)
{
    const float BN_INV = 0.9999950000374997f;
    int pt = blockIdx.x;
    int b = pt >> 10;
    __shared__ int nb[40];
    if (threadIdx.x < 40) nb[threadIdx.x] = IDX[pt * 40 + threadIdx.x];
    __syncthreads();
    int ld = 2 * Co;
    long long bbase = (long long)(b << 10) * ld;
    for (int o = threadIdx.x; o < Co; o += blockDim.x) {
        float mx = -CUDART_INF_F, mn = CUDART_INF_F;
#pragma unroll 8
        for (int k = 0; k < 40; k++) {
            float v = PQ[bbase + (long long)nb[k] * ld + o];
            mx = fmaxf(mx, v);
            mn = fminf(mn, v);
        }
        float q  = PQ[(long long)pt * ld + Co + o];
        float gg = g[o];
        float y = (gg >= 0.f ? mx : mn) + q;
        y = gg * (y * BN_INV) + bb[o];
        y = y > 0.f ? y : 0.2f * y;
        OUT[(long long)pt * ldo + o] = y;
    }
}

// ---------------- gmax init / decode ----------------------------------------
__global__ void gmax_init(unsigned* __restrict__ g)
{
    g[blockIdx.x * 1024 + threadIdx.x] = 0u;
}

__global__ void decode_out(const unsigned* __restrict__ g,
                           const float* __restrict__ bf, float* __restrict__ out)
{
    int i = blockIdx.x * 256 + threadIdx.x;
    unsigned e = g[i];
    unsigned u = (e & 0x80000000u) ? (e ^ 0x80000000u) : ~e;
    out[i] = __uint_as_float(u) + bf[i & 1023];
}

// ---------------- launch -----------------------------------------------------
extern "C" void kernel_launch(void* const* d_in, const int* in_sizes, int n_in,
                              void* d_out, int out_size)
{
    (void)in_sizes; (void)n_in; (void)out_size;
    const float* x  = (const float*)d_in[0];
    const float* w[4]  = {(const float*)d_in[1], (const float*)d_in[4],
                          (const float*)d_in[7], (const float*)d_in[10]};
    const float* g[4]  = {(const float*)d_in[2], (const float*)d_in[5],
                          (const float*)d_in[8], (const float*)d_in[11]};
    const float* bb[4] = {(const float*)d_in[3], (const float*)d_in[6],
                          (const float*)d_in[9], (const float*)d_in[12]};
    const float* wf = (const float*)d_in[13];
    const float* bf = (const float*)d_in[14];
    float* out = (float*)d_out;

    float *dist, *sq, *pq, *cat, *wpq; int* idx; unsigned* gm;
    uint32_t *ahi, *alo, *whi, *wlo, *fhi, *flo, *chi, *clo;
    cudaGetSymbolAddress((void**)&dist, d_dist);
    cudaGetSymbolAddress((void**)&sq,   d_sq);
    cudaGetSymbolAddress((void**)&idx,  d_idx);
    cudaGetSymbolAddress((void**)&pq,   d_pq);
    cudaGetSymbolAddress((void**)&cat,  d_cat);
    cudaGetSymbolAddress((void**)&wpq,  d_wpq);
    cudaGetSymbolAddress((void**)&gm,   d_gmax);
    cudaGetSymbolAddress((void**)&ahi,  d_ahi);
    cudaGetSymbolAddress((void**)&alo,  d_alo);
    cudaGetSymbolAddress((void**)&whi,  d_whi);
    cudaGetSymbolAddress((void**)&wlo,  d_wlo);
    cudaGetSymbolAddress((void**)&fhi,  d_fhi);
    cudaGetSymbolAddress((void**)&flo,  d_flo);
    cudaGetSymbolAddress((void**)&chi,  d_chi);
    cudaGetSymbolAddress((void**)&clo,  d_clo);

    cudaFuncSetAttribute(tgemm, cudaFuncAttributeMaxDynamicSharedMemorySize,
                         HG_SMEM);

    const int Cs[4]   = {3, 64, 64, 128};
    const int Cos[4]  = {64, 64, 128, 256};
    const int offs[4] = {0, 64, 128, 256};
    const int woff[4] = {0, 1024, 9216, 25600};

    // layer 0 (lda=3: FFMA path).  launch #4 = topk l0 (profiled).
    gmax_init<<<16, 1024>>>(gm);
    sq_kernel<<<2048, 256>>>(x, 3, 3, sq);
    sgemm128<<<dim3(36, 1, 16), 256>>>(
        x, 3, 1024LL * 3, x, 3, 1024LL * 3, sq,
        dist, 1024, 1024LL * 1024, 1024, 1024, 3, 1);
    topk40_kernel<<<16384, 256>>>(dist, idx);
    for (int l = 0; l < 4; l++)
        wprep_kernel<<<(Cos[l] * Cs[l] + 255) / 256, 256>>>(w[l], wpq + woff[l],
                                                            Cos[l], Cs[l]);
    cvt1d<<<(92160 / 4 + 255) / 256, 256>>>(wpq, whi, wlo, 92160 / 4);
    cvt1d<<<(1024 * 512 / 4 + 255) / 256, 256>>>(wf, fhi, flo, 1024 * 512 / 4);
    sgemm128<<<dim3(128, 1, 1), 256>>>(
        x, 3, 0, wpq, 3, 0, nullptr,
        pq, 128, 0, 16384, 128, 3, 0);
    edge_gathermax<<<16384, 64>>>(pq, idx, g[0], bb[0], cat + offs[0], 64, 512);

    // layers 1-3 on tensor cores
    for (int l = 1; l < 4; l++) {
        int C = Cs[l], Co = Cos[l];
        const float* A = cat + offs[l - 1];

        sq_kernel<<<2048, 256>>>(A, 512, C, sq);
        cvt2d<<<(16384 * C / 4 + 255) / 256, 256>>>(A, 512, C, ahi, alo);
        tgemm<<<dim3(36, 1, 16), 256, HG_SMEM>>>(
            ahi, alo, C, 1024LL * C, nullptr, nullptr, 0, sq,
            dist, 1024, 1024LL * 1024, 1024, C, 1, nullptr);
        topk40_kernel<<<16384, 256>>>(dist, idx);
        tgemm<<<dim3(128, (2 * Co) / 128, 1), 256, HG_SMEM>>>(
            ahi, alo, C, 0, whi + woff[l], wlo + woff[l], C, nullptr,
            pq, 2 * Co, 0, 2 * Co, C, 0, nullptr);
        edge_gathermax<<<16384, Co>>>(pq, idx, g[l], bb[l], cat + offs[l], Co, 512);
    }

    // final linear 512 -> 1024 (tf32x3, fused max over N)
    cvt1d<<<(16384 * 512 / 4 + 255) / 256, 256>>>(cat, chi, clo, 16384 * 512 / 4);
    tgemm<<<dim3(128, 8, 1), 256, HG_SMEM>>>(
        chi, clo, 512, 0, fhi, flo, 512, nullptr,
        dist, 0, 0, 1024, 512, 2, gm);
    decode_out<<<64, 256>>>(gm, bf, out);
}

// round 9
// speedup vs baseline: 1.8564x; 1.8564x over previous
#include <cuda_runtime.h>
#include <math_constants.h>
#include <cstdint>

// ---------------- scratch (static device globals; no allocation) ------------
__device__ float    d_dist[16 * 1024 * 1024];
__device__ float    d_sq  [16 * 1024];
__device__ int      d_idx [16 * 1024 * 40];
__device__ float    d_pq  [16 * 1024 * 512];
__device__ float    d_cat [16 * 1024 * 512];
__device__ float    d_wpq [92160];
__device__ unsigned d_gmax[16 * 1024];
__device__ uint32_t d_ahi[16 * 1024 * 128], d_alo[16 * 1024 * 128];
__device__ uint32_t d_whi[92160],           d_wlo[92160];
__device__ uint32_t d_fhi[1024 * 512],      d_flo[1024 * 512];
__device__ uint32_t d_chi[16 * 1024 * 512], d_clo[16 * 1024 * 512];

static __device__ __forceinline__ unsigned encf(float v) {
    unsigned u = __float_as_uint(v);
    return (u & 0x80000000u) ? ~u : (u | 0x80000000u);
}
static __device__ __forceinline__ void cvt_split(float v, uint32_t& h, uint32_t& l) {
    asm("cvt.rna.tf32.f32 %0, %1;" : "=r"(h) : "f"(v));
    float r = v - __uint_as_float(h);
    asm("cvt.rna.tf32.f32 %0, %1;" : "=r"(l) : "f"(r));
}
static __device__ __forceinline__ void mma_tf32(float* c, uint32_t a0, uint32_t a1,
                                                uint32_t a2, uint32_t a3,
                                                uint32_t b0, uint32_t b1) {
    asm volatile(
        "mma.sync.aligned.m16n8k8.row.col.f32.tf32.tf32.f32 "
        "{%0,%1,%2,%3}, {%4,%5,%6,%7}, {%8,%9}, {%0,%1,%2,%3};"
        : "+f"(c[0]), "+f"(c[1]), "+f"(c[2]), "+f"(c[3])
        : "r"(a0), "r"(a1), "r"(a2), "r"(a3), "r"(b0), "r"(b1));
}

static constexpr int HG_STRIDE = 24;
static constexpr int HG_ARR = 128 * HG_STRIDE;
static constexpr int HG_SMEM = 4 * HG_ARR * 4;   // 49152 bytes

static __device__ __forceinline__ int sidx(int k) {
    int ks = k >> 3, kk = k & 7;
    return ks * 8 + ((kk & 3) << 1) + (kk >> 2);
}

// ---------------- conversion kernels ----------------------------------------
__global__ void cvt1d(const float* __restrict__ src, uint32_t* __restrict__ hi,
                      uint32_t* __restrict__ lo, int n4)
{
    int i = blockIdx.x * 256 + threadIdx.x;
    if (i >= n4) return;
    float4 v = ((const float4*)src)[i];
    uint4 h, l;
    cvt_split(v.x, h.x, l.x);
    cvt_split(v.y, h.y, l.y);
    cvt_split(v.z, h.z, l.z);
    cvt_split(v.w, h.w, l.w);
    ((uint4*)hi)[i] = h;
    ((uint4*)lo)[i] = l;
}

__global__ void cvt2d(const float* __restrict__ src, int ld, int cols,
                      uint32_t* __restrict__ hi, uint32_t* __restrict__ lo)
{
    int i = blockIdx.x * 256 + threadIdx.x;
    int c4s = cols >> 2;
    int r = i / c4s, c4 = i - r * c4s;
    if (r >= 16384) return;
    float4 v = *(const float4*)&src[(size_t)r * ld + c4 * 4];
    uint4 h, l;
    cvt_split(v.x, h.x, l.x);
    cvt_split(v.y, h.y, l.y);
    cvt_split(v.z, h.z, l.z);
    cvt_split(v.w, h.w, l.w);
    *(uint4*)&hi[(size_t)r * cols + c4 * 4] = h;
    *(uint4*)&lo[(size_t)r * cols + c4 * 4] = l;
}

// ============ generalized tf32x3 tensor GEMM: C = A(..xK) * B(NxK)^T ========
__global__ void __launch_bounds__(256, 2)
tgemm(const uint32_t* __restrict__ Ahi, const uint32_t* __restrict__ Alo,
      int lda, long long sA,
      const uint32_t* __restrict__ Bhi, const uint32_t* __restrict__ Blo,
      int ldb,
      const float* __restrict__ sq,
      float* __restrict__ C, int ldc, long long sC,
      int N, int K, int mode, unsigned* __restrict__ gmax)
{
    extern __shared__ uint32_t dsm[];
    uint32_t* sAh = dsm;
    uint32_t* sAl = sAh + HG_ARR;
    uint32_t* sBh = sAl + HG_ARR;
    uint32_t* sBl = sBh + HG_ARR;

    int bz = blockIdx.z;
    Ahi += (long long)bz * sA;
    Alo += (long long)bz * sA;
    const float* sqb = sq ? sq + (long long)bz * 1024 : nullptr;
    C += (long long)bz * sC;

    int bi, bj;
    if (mode == 1) {
        int nb = N >> 7;
        int p = blockIdx.x;
        bi = 0;
        while (p >= nb - bi) { p -= nb - bi; bi++; }
        bj = bi + p;
    } else { bi = blockIdx.x; bj = blockIdx.y; }
    const int row0 = bi * 128, col0 = bj * 128;

    const uint32_t* Bh2 = (mode == 1) ? Ahi : Bhi;
    const uint32_t* Bl2 = (mode == 1) ? Alo : Blo;
    const int ldb2 = (mode == 1) ? lda : ldb;

    const int tid = threadIdx.x;
    const int wid = tid >> 5, lane = tid & 31;
    const int wr = wid >> 2, wc = wid & 3;
    const int g = lane >> 2, t = lane & 3;
    const int lrow = tid >> 2, lc4 = tid & 3;

    float acc[4][4][4];
#pragma unroll
    for (int mt = 0; mt < 4; mt++)
#pragma unroll
        for (int nt = 0; nt < 4; nt++)
#pragma unroll
            for (int i = 0; i < 4; i++) acc[mt][nt][i] = 0.f;

    const int nchunk = K >> 4;
    for (int ch = 0; ch < nchunk; ch++) {
        const int k0 = ch * 16;
        __syncthreads();
#pragma unroll
        for (int i = 0; i < 2; i++) {
            int row = i * 64 + lrow;
            uint4 vah = *(const uint4*)&Ahi[(size_t)(row0 + row) * lda + k0 + lc4 * 4];
            uint4 val = *(const uint4*)&Alo[(size_t)(row0 + row) * lda + k0 + lc4 * 4];
            uint4 vbh = *(const uint4*)&Bh2[(size_t)(col0 + row) * ldb2 + k0 + lc4 * 4];
            uint4 vbl = *(const uint4*)&Bl2[(size_t)(col0 + row) * ldb2 + k0 + lc4 * 4];
            uint32_t eah[4] = {vah.x, vah.y, vah.z, vah.w};
            uint32_t eal[4] = {val.x, val.y, val.z, val.w};
            uint32_t ebh[4] = {vbh.x, vbh.y, vbh.z, vbh.w};
            uint32_t ebl[4] = {vbl.x, vbl.y, vbl.z, vbl.w};
#pragma unroll
            for (int j = 0; j < 4; j++) {
                int s = sidx(lc4 * 4 + j);
                sAh[row * HG_STRIDE + s] = eah[j];
                sAl[row * HG_STRIDE + s] = eal[j];
                sBh[row * HG_STRIDE + s] = ebh[j];
                sBl[row * HG_STRIDE + s] = ebl[j];
            }
        }
        __syncthreads();

#pragma unroll
        for (int ks = 0; ks < 2; ks++) {
            uint2 bh[4], bl[4];
#pragma unroll
            for (int nt = 0; nt < 4; nt++) {
                int nb_ = wc * 32 + nt * 8 + g;
                bh[nt] = *(const uint2*)&sBh[nb_ * HG_STRIDE + ks * 8 + 2 * t];
                bl[nt] = *(const uint2*)&sBl[nb_ * HG_STRIDE + ks * 8 + 2 * t];
            }
            uint32_t af[4][4];
#pragma unroll
            for (int mt = 0; mt < 4; mt++) {
                int rb = wr * 64 + mt * 16 + g;
                uint2 a02 = *(const uint2*)&sAh[rb * HG_STRIDE + ks * 8 + 2 * t];
                uint2 a13 = *(const uint2*)&sAh[(rb + 8) * HG_STRIDE + ks * 8 + 2 * t];
                af[mt][0] = a02.x; af[mt][1] = a13.x;
                af[mt][2] = a02.y; af[mt][3] = a13.y;
            }
#pragma unroll
            for (int nt = 0; nt < 4; nt++)
#pragma unroll
                for (int mt = 0; mt < 4; mt++) {
                    mma_tf32(acc[mt][nt], af[mt][0], af[mt][1], af[mt][2],
                             af[mt][3], bh[nt].x, bh[nt].y);
                    mma_tf32(acc[mt][nt], af[mt][0], af[mt][1], af[mt][2],
                             af[mt][3], bl[nt].x, bl[nt].y);
                }
#pragma unroll
            for (int mt = 0; mt < 4; mt++) {
                int rb = wr * 64 + mt * 16 + g;
                uint2 a02 = *(const uint2*)&sAl[rb * HG_STRIDE + ks * 8 + 2 * t];
                uint2 a13 = *(const uint2*)&sAl[(rb + 8) * HG_STRIDE + ks * 8 + 2 * t];
                af[mt][0] = a02.x; af[mt][1] = a13.x;
                af[mt][2] = a02.y; af[mt][3] = a13.y;
            }
#pragma unroll
            for (int nt = 0; nt < 4; nt++)
#pragma unroll
                for (int mt = 0; mt < 4; mt++)
                    mma_tf32(acc[mt][nt], af[mt][0], af[mt][1], af[mt][2],
                             af[mt][3], bh[nt].x, bh[nt].y);
        }
    }

    if (mode == 2) {
        const int batch = row0 >> 10;
#pragma unroll
        for (int nt = 0; nt < 4; nt++)
#pragma unroll
            for (int j = 0; j < 2; j++) {
                float v = -CUDART_INF_F;
#pragma unroll
                for (int mt = 0; mt < 4; mt++)
                    v = fmaxf(v, fmaxf(acc[mt][nt][j], acc[mt][nt][j + 2]));
#pragma unroll
                for (int off = 4; off < 32; off <<= 1)
                    v = fmaxf(v, __shfl_xor_sync(0xffffffffu, v, off));
                if (lane < 4) {
                    int col = col0 + wc * 32 + nt * 8 + 2 * lane + j;
                    atomicMax(&gmax[batch * 1024 + col], encf(v));
                }
            }
        return;
    }

#pragma unroll
    for (int mt = 0; mt < 4; mt++)
#pragma unroll
        for (int nt = 0; nt < 4; nt++) {
            int r = row0 + wr * 64 + mt * 16 + g;
            int c = col0 + wc * 32 + nt * 8 + 2 * t;
            float v0 = acc[mt][nt][0], v1 = acc[mt][nt][1];
            float v2 = acc[mt][nt][2], v3 = acc[mt][nt][3];
            if (mode == 1) {
                float sr0 = sqb[r & 1023], sr8 = sqb[(r + 8) & 1023];
                float sc0 = sqb[c & 1023], sc1 = sqb[(c + 1) & 1023];
                v0 = 2.f * v0 - sr0 - sc0; v1 = 2.f * v1 - sr0 - sc1;
                v2 = 2.f * v2 - sr8 - sc0; v3 = 2.f * v3 - sr8 - sc1;
            }
            *(float2*)&C[(size_t)r * ldc + c] = make_float2(v0, v1);
            *(float2*)&C[(size_t)(r + 8) * ldc + c] = make_float2(v2, v3);
            if (mode == 1 && bi != bj) {
                C[(size_t)c * ldc + r] = v0;
                C[(size_t)(c + 1) * ldc + r] = v1;
                C[(size_t)c * ldc + r + 8] = v2;
                C[(size_t)(c + 1) * ldc + r + 8] = v3;
            }
        }
}

// ---------------- 128x128x8 FFMA SGEMM (layer 0 only, lda=3) ---------------
__global__ void __launch_bounds__(256, 2)
sgemm128(const float* __restrict__ A, int lda, long long sA,
         const float* __restrict__ B, int ldb, long long sB,
         const float* __restrict__ sq,
         float* __restrict__ C, int ldc, long long sC,
         int M, int N, int K, int mode)
{
    int bz = blockIdx.z;
    A += (long long)bz * sA;
    B += (long long)bz * sB;
    C += (long long)bz * sC;
    const float* sqb = sq ? (sq + (long long)bz * M) : nullptr;

    int bi, bj;
    if (mode == 1) {
        int nb = N >> 7;
        int p = blockIdx.x;
        bi = 0;
        while (p >= nb - bi) { p -= nb - bi; bi++; }
        bj = bi + p;
    } else { bi = blockIdx.x; bj = blockIdx.y; }
    const int row0 = bi * 128;
    const int col0 = bj * 128;

    __shared__ float As[2][8][132];
    __shared__ float Bs[2][8][132];

    const int tid = threadIdx.x;
    const int lk = tid & 7;
    const int lm = tid >> 3;
    const int tx = tid & 15;
    const int ty = tid >> 4;

    float acc[8][8];
#pragma unroll
    for (int i = 0; i < 8; i++)
#pragma unroll
        for (int j = 0; j < 8; j++) acc[i][j] = 0.f;

    float pa[4], pb[4];
    const int nk = (K + 7) >> 3;

    {
        int k = lk;
        bool ok = (k < K);
#pragma unroll
        for (int j = 0; j < 4; j++) {
            int m = lm + 32 * j;
            pa[j] = ok ? A[(long long)(row0 + m) * lda + k] : 0.f;
            pb[j] = ok ? B[(long long)(col0 + m) * ldb + k] : 0.f;
        }
#pragma unroll
        for (int j = 0; j < 4; j++) {
            As[0][lk][lm + 32 * j] = pa[j];
            Bs[0][lk][lm + 32 * j] = pb[j];
        }
    }
    __syncthreads();

    for (int t = 0; t < nk; t++) {
        int cur = t & 1;
        if (t + 1 < nk) {
            int k = (t + 1) * 8 + lk;
            bool ok = (k < K);
#pragma unroll
            for (int j = 0; j < 4; j++) {
                int m = lm + 32 * j;
                pa[j] = ok ? A[(long long)(row0 + m) * lda + k] : 0.f;
                pb[j] = ok ? B[(long long)(col0 + m) * ldb + k] : 0.f;
            }
        }
#pragma unroll
        for (int kk = 0; kk < 8; kk++) {
            float a[8], b[8];
            *(float4*)&a[0] = *(const float4*)&As[cur][kk][ty * 4];
            *(float4*)&a[4] = *(const float4*)&As[cur][kk][64 + ty * 4];
            *(float4*)&b[0] = *(const float4*)&Bs[cur][kk][tx * 4];
            *(float4*)&b[4] = *(const float4*)&Bs[cur][kk][64 + tx * 4];
#pragma unroll
            for (int i = 0; i < 8; i++)
#pragma unroll
                for (int j = 0; j < 8; j++)
                    acc[i][j] += a[i] * b[j];
        }
        if (t + 1 < nk) {
            int nxt = cur ^ 1;
#pragma unroll
            for (int j = 0; j < 4; j++) {
                As[nxt][lk][lm + 32 * j] = pa[j];
                Bs[nxt][lk][lm + 32 * j] = pb[j];
            }
        }
        __syncthreads();
    }

#pragma unroll
    for (int ih = 0; ih < 2; ih++) {
#pragma unroll
        for (int i = 0; i < 4; i++) {
            int r = row0 + ih * 64 + ty * 4 + i;
            float srow = (mode == 1) ? sqb[r] : 0.f;
#pragma unroll
            for (int jh = 0; jh < 2; jh++) {
                float outv[4];
#pragma unroll
                for (int j = 0; j < 4; j++) {
                    float v = acc[ih * 4 + i][jh * 4 + j];
                    if (mode == 1)
                        v = (2.f * v - srow) - sqb[col0 + jh * 64 + tx * 4 + j];
                    outv[j] = v;
                }
                *(float4*)&C[(long long)r * ldc + col0 + jh * 64 + tx * 4] =
                    *(float4*)&outv[0];
            }
        }
    }

    if (mode == 1 && bi != bj) {
#pragma unroll
        for (int jh = 0; jh < 2; jh++)
#pragma unroll
            for (int j = 0; j < 4; j++) {
                int c = col0 + jh * 64 + tx * 4 + j;
                float sc = sqb[c];
#pragma unroll
                for (int ih = 0; ih < 2; ih++) {
                    int rb = row0 + ih * 64 + ty * 4;
                    float mv[4];
#pragma unroll
                    for (int i = 0; i < 4; i++)
                        mv[i] = (2.f * acc[ih * 4 + i][jh * 4 + j] - sqb[rb + i]) - sc;
                    *(float4*)&C[(long long)c * ldc + rb] = *(float4*)&mv[0];
                }
            }
    }
}

// ---------------- squared norms ---------------------------------------------
__global__ void sq_kernel(const float* __restrict__ H, int lda, int C,
                          float* __restrict__ SQ)
{
    int gwarp = (blockIdx.x * blockDim.x + threadIdx.x) >> 5;
    int lane = threadIdx.x & 31;
    if (gwarp >= 16 * 1024) return;
    const float* h = H + (long long)gwarp * lda;
    float s = 0.f;
    for (int c = lane; c < C; c += 32) { float v = h[c]; s += v * v; }
#pragma unroll
    for (int d = 16; d > 0; d >>= 1) s += __shfl_down_sync(0xffffffffu, s, d);
    if (lane == 0) SQ[gwarp] = s;
}

// ---------------- top-40 via byte-wise radix select -------------------------
// One block per row. Finds T = 40th largest encoded key, emits key>T plus the
// (40 - count(key>T)) lowest-index ties with key==T. Output order arbitrary
// (downstream max over the set is order-invariant).
__global__ void __launch_bounds__(256)
topk40_kernel(const float* __restrict__ S, int* __restrict__ IDX)
{
    int row = blockIdx.x;
    const float* s = S + (long long)row * 1024;
    int tid = threadIdx.x;
    int lane = tid & 31, w = tid >> 5;

    unsigned key[4];
    {
        float4 v = ((const float4*)s)[tid];
        key[0] = encf(v.x); key[1] = encf(v.y);
        key[2] = encf(v.z); key[3] = encf(v.w);
    }
    bool cand[4] = {true, true, true, true};

    __shared__ unsigned hist[256];
    __shared__ unsigned cntge[256];
    __shared__ unsigned wsum[8];
    __shared__ int shB;
    __shared__ unsigned shGT;
    __shared__ int outcnt, tiecnt;
    __shared__ int tielist[1024];

    unsigned prefix = 0;
    int kneed = 40;
    unsigned T = 0;
    int r = 0;
    bool done = false;

    for (int level = 0; level < 4 && !done; level++) {
        const int shift = 24 - 8 * level;
        hist[tid] = 0;
        __syncthreads();
#pragma unroll
        for (int j = 0; j < 4; j++)
            if (cand[j]) atomicAdd(&hist[(key[j] >> shift) & 255u], 1u);
        __syncthreads();

        // reverse inclusive scan: cntge[b] = sum_{b'>=b} hist[b']
        unsigned v = hist[255 - tid];
#pragma unroll
        for (int d = 1; d < 32; d <<= 1) {
            unsigned n = __shfl_up_sync(0xffffffffu, v, d);
            if (lane >= d) v += n;
        }
        if (lane == 31) wsum[w] = v;
        __syncthreads();
        if (tid == 0) {
            unsigned a = 0;
#pragma unroll
            for (int q = 0; q < 8; q++) { unsigned t2 = wsum[q]; wsum[q] = a; a += t2; }
        }
        __syncthreads();
        cntge[255 - tid] = v + wsum[w];
        __syncthreads();

        // boundary: largest b with cntge[b] >= kneed
        unsigned geb = cntge[tid];
        unsigned geb1 = (tid == 255) ? 0u : cntge[tid + 1];
        if (geb >= (unsigned)kneed && geb1 < (unsigned)kneed) {
            shB = tid;
            shGT = geb1;
        }
        __syncthreads();
        int B = shB;
        int gt = (int)shGT;
        int kn = kneed - gt;              // still needed within bucket B
        int hb = (int)hist[B];
        if (hb == kn) {                   // whole bucket included, exact
            T = (prefix | ((unsigned)B << shift)) - 1u;
            r = 0;
            done = true;
        } else if (shift == 0) {
            T = prefix | (unsigned)B;
            r = kn;
            done = true;
        } else {
            prefix |= (unsigned)B << shift;
            kneed = kn;
#pragma unroll
            for (int j = 0; j < 4; j++)
                cand[j] = cand[j] && (((key[j] >> shift) & 255u) == (unsigned)B);
        }
        __syncthreads();
    }

    if (tid == 0) { outcnt = 0; tiecnt = 0; }
    __syncthreads();

#pragma unroll
    for (int j = 0; j < 4; j++) {
        int m = tid * 4 + j;
        if (key[j] > T) {
            int slot = atomicAdd(&outcnt, 1);
            IDX[row * 40 + slot] = m;
        } else if (r > 0 && key[j] == T) {
            int t2 = atomicAdd(&tiecnt, 1);
            tielist[t2] = m;
        }
    }
    __syncthreads();

    if (r > 0) {
        int tt = tiecnt;
        for (int p = tid; p < tt; p += 256) {
            int mi = tielist[p];
            int rk = 0;
            for (int q = 0; q < tt; q++) rk += (tielist[q] < mi);
            if (rk < r) {
                int slot = atomicAdd(&outcnt, 1);
                IDX[row * 40 + slot] = mi;
            }
        }
    }
}

// ---------------- weight transform ------------------------------------------
__global__ void wprep_kernel(const float* __restrict__ W, float* __restrict__ WPQ,
                             int Co, int C)
{
    int i = blockIdx.x * blockDim.x + threadIdx.x;
    if (i >= Co * C) return;
    int o = i / C, c = i % C;
    float wl = W[o * 2 * C + c];
    float wr = W[o * 2 * C + C + c];
    WPQ[o * C + c] = wl;
    WPQ[(Co + o) * C + c] = wr - wl;
}

// ---------------- gather-max + BN affine + LeakyReLU ------------------------
__global__ void edge_gathermax(const float* __restrict__ PQ,
                               const int* __restrict__ IDX,
                               const float* __restrict__ g,
                               const float* __restrict__ bb,
                               float* __restrict__ OUT,
                               int Co, int ldo)
{
    const float BN_INV = 0.9999950000374997f;
    int pt = blockIdx.x;
    int b = pt >> 10;
    __shared__ int nb[40];
    if (threadIdx.x < 40) nb[threadIdx.x] = IDX[pt * 40 + threadIdx.x];
    __syncthreads();
    int ld = 2 * Co;
    long long bbase = (long long)(b << 10) * ld;
    for (int o = threadIdx.x; o < Co; o += blockDim.x) {
        float mx = -CUDART_INF_F, mn = CUDART_INF_F;
#pragma unroll 8
        for (int k = 0; k < 40; k++) {
            float v = PQ[bbase + (long long)nb[k] * ld + o];
            mx = fmaxf(mx, v);
            mn = fminf(mn, v);
        }
        float q  = PQ[(long long)pt * ld + Co + o];
        float gg = g[o];
        float y = (gg >= 0.f ? mx : mn) + q;
        y = gg * (y * BN_INV) + bb[o];
        y = y > 0.f ? y : 0.2f * y;
        OUT[(long long)pt * ldo + o] = y;
    }
}

// ---------------- gmax init / decode ----------------------------------------
__global__ void gmax_init(unsigned* __restrict__ g)
{
    g[blockIdx.x * 1024 + threadIdx.x] = 0u;
}

__global__ void decode_out(const unsigned* __restrict__ g,
                           const float* __restrict__ bf, float* __restrict__ out)
{
    int i = blockIdx.x * 256 + threadIdx.x;
    unsigned e = g[i];
    unsigned u = (e & 0x80000000u) ? (e ^ 0x80000000u) : ~e;
    out[i] = __uint_as_float(u) + bf[i & 1023];
}

// ---------------- launch -----------------------------------------------------
extern "C" void kernel_launch(void* const* d_in, const int* in_sizes, int n_in,
                              void* d_out, int out_size)
{
    (void)in_sizes; (void)n_in; (void)out_size;
    const float* x  = (const float*)d_in[0];
    const float* w[4]  = {(const float*)d_in[1], (const float*)d_in[4],
                          (const float*)d_in[7], (const float*)d_in[10]};
    const float* g[4]  = {(const float*)d_in[2], (const float*)d_in[5],
                          (const float*)d_in[8], (const float*)d_in[11]};
    const float* bb[4] = {(const float*)d_in[3], (const float*)d_in[6],
                          (const float*)d_in[9], (const float*)d_in[12]};
    const float* wf = (const float*)d_in[13];
    const float* bf = (const float*)d_in[14];
    float* out = (float*)d_out;

    float *dist, *sq, *pq, *cat, *wpq; int* idx; unsigned* gm;
    uint32_t *ahi, *alo, *whi, *wlo, *fhi, *flo, *chi, *clo;
    cudaGetSymbolAddress((void**)&dist, d_dist);
    cudaGetSymbolAddress((void**)&sq,   d_sq);
    cudaGetSymbolAddress((void**)&idx,  d_idx);
    cudaGetSymbolAddress((void**)&pq,   d_pq);
    cudaGetSymbolAddress((void**)&cat,  d_cat);
    cudaGetSymbolAddress((void**)&wpq,  d_wpq);
    cudaGetSymbolAddress((void**)&gm,   d_gmax);
    cudaGetSymbolAddress((void**)&ahi,  d_ahi);
    cudaGetSymbolAddress((void**)&alo,  d_alo);
    cudaGetSymbolAddress((void**)&whi,  d_whi);
    cudaGetSymbolAddress((void**)&wlo,  d_wlo);
    cudaGetSymbolAddress((void**)&fhi,  d_fhi);
    cudaGetSymbolAddress((void**)&flo,  d_flo);
    cudaGetSymbolAddress((void**)&chi,  d_chi);
    cudaGetSymbolAddress((void**)&clo,  d_clo);

    cudaFuncSetAttribute(tgemm, cudaFuncAttributeMaxDynamicSharedMemorySize,
                         HG_SMEM);

    const int Cs[4]   = {3, 64, 64, 128};
    const int Cos[4]  = {64, 64, 128, 256};
    const int offs[4] = {0, 64, 128, 256};
    const int woff[4] = {0, 1024, 9216, 25600};

    // layer 0 (lda=3: FFMA path).  launch #4 = topk l0 (profiled slot).
    gmax_init<<<16, 1024>>>(gm);
    sq_kernel<<<2048, 256>>>(x, 3, 3, sq);
    sgemm128<<<dim3(36, 1, 16), 256>>>(
        x, 3, 1024LL * 3, x, 3, 1024LL * 3, sq,
        dist, 1024, 1024LL * 1024, 1024, 1024, 3, 1);
    topk40_kernel<<<16384, 256>>>(dist, idx);
    for (int l = 0; l < 4; l++)
        wprep_kernel<<<(Cos[l] * Cs[l] + 255) / 256, 256>>>(w[l], wpq + woff[l],
                                                            Cos[l], Cs[l]);
    cvt1d<<<(92160 / 4 + 255) / 256, 256>>>(wpq, whi, wlo, 92160 / 4);
    cvt1d<<<(1024 * 512 / 4 + 255) / 256, 256>>>(wf, fhi, flo, 1024 * 512 / 4);
    sgemm128<<<dim3(128, 1, 1), 256>>>(
        x, 3, 0, wpq, 3, 0, nullptr,
        pq, 128, 0, 16384, 128, 3, 0);
    edge_gathermax<<<16384, 64>>>(pq, idx, g[0], bb[0], cat + offs[0], 64, 512);

    // layers 1-3 on tensor cores
    for (int l = 1; l < 4; l++) {
        int C = Cs[l], Co = Cos[l];
        const float* A = cat + offs[l - 1];

        sq_kernel<<<2048, 256>>>(A, 512, C, sq);
        cvt2d<<<(16384 * C / 4 + 255) / 256, 256>>>(A, 512, C, ahi, alo);
        tgemm<<<dim3(36, 1, 16), 256, HG_SMEM>>>(
            ahi, alo, C, 1024LL * C, nullptr, nullptr, 0, sq,
            dist, 1024, 1024LL * 1024, 1024, C, 1, nullptr);
        topk40_kernel<<<16384, 256>>>(dist, idx);
        tgemm<<<dim3(128, (2 * Co) / 128, 1), 256, HG_SMEM>>>(
            ahi, alo, C, 0, whi + woff[l], wlo + woff[l], C, nullptr,
            pq, 2 * Co, 0, 2 * Co, C, 0, nullptr);
        edge_gathermax<<<16384, Co>>>(pq, idx, g[l], bb[l], cat + offs[l], Co, 512);
    }

    // final linear 512 -> 1024 (tf32x3, fused max over N)
    cvt1d<<<(16384 * 512 / 4 + 255) / 256, 256>>>(cat, chi, clo, 16384 * 512 / 4);
    tgemm<<<dim3(128, 8, 1), 256, HG_SMEM>>>(
        chi, clo, 512, 0, fhi, flo, 512, nullptr,
        dist, 0, 0, 1024, 512, 2, gm);
    decode_out<<<64, 256>>>(gm, bf, out);
}

// round 10
// speedup vs baseline: 2.6109x; 1.4064x over previous
#include <cuda_runtime.h>
#include <cuda_fp16.h>
#include <math_constants.h>
#include <cstdint>

// ---------------- scratch (static device globals; no allocation) ------------
__device__ float    d_dist[16 * 1024 * 1024];
__device__ float    d_sq  [16 * 1024];
__device__ int      d_idx [16 * 1024 * 40];
__device__ float    d_pq  [16 * 1024 * 512];
__device__ float    d_cat [16 * 1024 * 512];
__device__ float    d_wpq [92160];
__device__ unsigned d_gmax[16 * 1024];
// fp16-split planes (packed half2 words, k-pairs)
__device__ uint32_t d_ah[16 * 1024 * 64], d_al[16 * 1024 * 64];   // cat slice (C<=128)
__device__ uint32_t d_wh[46080],          d_wl[46080];            // wpq
__device__ uint32_t d_fh[1024 * 256],     d_fl[1024 * 256];       // wf
__device__ uint32_t d_ch[16 * 1024 * 256], d_cl[16 * 1024 * 256]; // full cat

static __device__ __forceinline__ unsigned encf(float v) {
    unsigned u = __float_as_uint(v);
    return (u & 0x80000000u) ? ~u : (u | 0x80000000u);
}
static __device__ __forceinline__ void hsplit2(float a, float b,
                                               uint32_t& h, uint32_t& l) {
    __half ha = __float2half_rn(a), hb = __float2half_rn(b);
    __half la = __float2half_rn(a - __half2float(ha));
    __half lb = __float2half_rn(b - __half2float(hb));
    __half2 H = __halves2half2(ha, hb), L = __halves2half2(la, lb);
    h = *(uint32_t*)&H;
    l = *(uint32_t*)&L;
}
static __device__ __forceinline__ void mma_f16(float* c, uint32_t a0, uint32_t a1,
                                               uint32_t a2, uint32_t a3,
                                               uint32_t b0, uint32_t b1) {
    asm volatile(
        "mma.sync.aligned.m16n8k16.row.col.f32.f16.f16.f32 "
        "{%0,%1,%2,%3}, {%4,%5,%6,%7}, {%8,%9}, {%0,%1,%2,%3};"
        : "+f"(c[0]), "+f"(c[1]), "+f"(c[2]), "+f"(c[3])
        : "r"(a0), "r"(a1), "r"(a2), "r"(a3), "r"(b0), "r"(b1));
}

static constexpr int KSW   = 128 * 12;     // words per ks-plane (k16 sub-chunk)
static constexpr int PLW   = 2 * KSW;      // 3072 words per matrix-plane
static constexpr int HSMEM = 4 * PLW * 4;  // 49152 bytes

// ---------------- conversion kernels (fp32 -> packed half2 hi/lo planes) ----
__global__ void cvt1d_h(const float* __restrict__ src, uint32_t* __restrict__ hi,
                        uint32_t* __restrict__ lo, int n4)
{
    int i = blockIdx.x * 256 + threadIdx.x;
    if (i >= n4) return;
    float4 v = ((const float4*)src)[i];
    uint2 h, l;
    hsplit2(v.x, v.y, h.x, l.x);
    hsplit2(v.z, v.w, h.y, l.y);
    ((uint2*)hi)[i] = h;
    ((uint2*)lo)[i] = l;
}

__global__ void cvt2d_h(const float* __restrict__ src, int ld, int cols,
                        uint32_t* __restrict__ hi, uint32_t* __restrict__ lo)
{
    int i = blockIdx.x * 256 + threadIdx.x;
    int c4s = cols >> 2;
    int r = i / c4s, c4 = i - r * c4s;
    if (r >= 16384) return;
    float4 v = *(const float4*)&src[(size_t)r * ld + c4 * 4];
    uint2 h, l;
    hsplit2(v.x, v.y, h.x, l.x);
    hsplit2(v.z, v.w, h.y, l.y);
    ((uint2*)hi)[r * (cols >> 2) + c4] = h;
    ((uint2*)lo)[r * (cols >> 2) + c4] = l;
}

// ============ fp16x3 tensor GEMM: C = A(..xK) * B(NxK)^T ====================
// mode 0: plain store.  mode 1: dist-symmetric (B=A, upper-tri, +mirror).
// mode 2: fused max over rows -> atomicMax(gmax).
// lda/ldb are in WORDS (half2 pairs); K in elements (multiple of 32).
__global__ void __launch_bounds__(256, 2)
hgemm(const uint32_t* __restrict__ Ah, const uint32_t* __restrict__ Al,
      int ldaw, long long sA,
      const uint32_t* __restrict__ Bh, const uint32_t* __restrict__ Bl,
      int ldbw,
      const float* __restrict__ sq,
      float* __restrict__ C, int ldc, long long sC,
      int N, int K, int mode, unsigned* __restrict__ gmax)
{
    extern __shared__ uint32_t dsm[];
    uint32_t* sAh = dsm;
    uint32_t* sAl = sAh + PLW;
    uint32_t* sBh = sAl + PLW;
    uint32_t* sBl = sBh + PLW;

    int bz = blockIdx.z;
    Ah += (long long)bz * sA;
    Al += (long long)bz * sA;
    const float* sqb = sq ? sq + (long long)bz * 1024 : nullptr;
    C += (long long)bz * sC;

    int bi, bj;
    if (mode == 1) {
        int nb = N >> 7;
        int p = blockIdx.x;
        bi = 0;
        while (p >= nb - bi) { p -= nb - bi; bi++; }
        bj = bi + p;
    } else { bi = blockIdx.x; bj = blockIdx.y; }
    const int row0 = bi * 128, col0 = bj * 128;

    const uint32_t* Bh2 = (mode == 1) ? Ah : Bh;
    const uint32_t* Bl2 = (mode == 1) ? Al : Bl;
    const int ldb2 = (mode == 1) ? ldaw : ldbw;

    const int tid = threadIdx.x;
    const int wid = tid >> 5, lane = tid & 31;
    const int wr = wid >> 2, wc = wid & 3;
    const int g = lane >> 2, t = lane & 3;

    float acc[4][4][4];
#pragma unroll
    for (int mt = 0; mt < 4; mt++)
#pragma unroll
        for (int nt = 0; nt < 4; nt++)
#pragma unroll
            for (int i = 0; i < 4; i++) acc[mt][nt][i] = 0.f;

    const int nch = K >> 5;
    for (int ch = 0; ch < nch; ch++) {
        const int k0w = ch * 16;
        __syncthreads();
#pragma unroll
        for (int i = 0; i < 2; i++) {
            int id4 = i * 256 + tid;          // 512 uint4 per plane
            int row = id4 >> 2;
            int w4 = id4 & 3;                 // uint4 within 16-word row-chunk
            int ks = w4 >> 1, wi = (w4 & 1) * 4;
            size_t ga = (size_t)(row0 + row) * ldaw + k0w + w4 * 4;
            size_t gb = (size_t)(col0 + row) * ldb2 + k0w + w4 * 4;
            uint4 vah = *(const uint4*)&Ah[ga];
            uint4 val = *(const uint4*)&Al[ga];
            uint4 vbh = *(const uint4*)&Bh2[gb];
            uint4 vbl = *(const uint4*)&Bl2[gb];
            int so = ks * KSW + row * 12 + wi;
            *(uint4*)&sAh[so] = vah;
            *(uint4*)&sAl[so] = val;
            *(uint4*)&sBh[so] = vbh;
            *(uint4*)&sBl[so] = vbl;
        }
        __syncthreads();

#pragma unroll
        for (int ks = 0; ks < 2; ks++) {
            const uint32_t* pAh = sAh + ks * KSW;
            const uint32_t* pAl = sAl + ks * KSW;
            const uint32_t* pBh = sBh + ks * KSW;
            const uint32_t* pBl = sBl + ks * KSW;

            uint32_t bh0[4], bh1[4], bl0[4], bl1[4];
#pragma unroll
            for (int nt = 0; nt < 4; nt++) {
                int nb_ = wc * 32 + nt * 8 + g;
                bh0[nt] = pBh[nb_ * 12 + t];
                bh1[nt] = pBh[nb_ * 12 + 4 + t];
                bl0[nt] = pBl[nb_ * 12 + t];
                bl1[nt] = pBl[nb_ * 12 + 4 + t];
            }
            uint32_t a[4][4];
#pragma unroll
            for (int mt = 0; mt < 4; mt++) {
                int rb = wr * 64 + mt * 16 + g;
                a[mt][0] = pAh[rb * 12 + t];
                a[mt][1] = pAh[(rb + 8) * 12 + t];
                a[mt][2] = pAh[rb * 12 + 4 + t];
                a[mt][3] = pAh[(rb + 8) * 12 + 4 + t];
            }
#pragma unroll
            for (int nt = 0; nt < 4; nt++)
#pragma unroll
                for (int mt = 0; mt < 4; mt++) {
                    mma_f16(acc[mt][nt], a[mt][0], a[mt][1], a[mt][2], a[mt][3],
                            bh0[nt], bh1[nt]);
                    mma_f16(acc[mt][nt], a[mt][0], a[mt][1], a[mt][2], a[mt][3],
                            bl0[nt], bl1[nt]);
                }
#pragma unroll
            for (int mt = 0; mt < 4; mt++) {
                int rb = wr * 64 + mt * 16 + g;
                a[mt][0] = pAl[rb * 12 + t];
                a[mt][1] = pAl[(rb + 8) * 12 + t];
                a[mt][2] = pAl[rb * 12 + 4 + t];
                a[mt][3] = pAl[(rb + 8) * 12 + 4 + t];
            }
#pragma unroll
            for (int nt = 0; nt < 4; nt++)
#pragma unroll
                for (int mt = 0; mt < 4; mt++)
                    mma_f16(acc[mt][nt], a[mt][0], a[mt][1], a[mt][2], a[mt][3],
                            bh0[nt], bh1[nt]);
        }
    }

    if (mode == 2) {
        const int batch = row0 >> 10;
#pragma unroll
        for (int nt = 0; nt < 4; nt++)
#pragma unroll
            for (int j = 0; j < 2; j++) {
                float v = -CUDART_INF_F;
#pragma unroll
                for (int mt = 0; mt < 4; mt++)
                    v = fmaxf(v, fmaxf(acc[mt][nt][j], acc[mt][nt][j + 2]));
#pragma unroll
                for (int off = 4; off < 32; off <<= 1)
                    v = fmaxf(v, __shfl_xor_sync(0xffffffffu, v, off));
                if (lane < 4) {
                    int col = col0 + wc * 32 + nt * 8 + 2 * lane + j;
                    atomicMax(&gmax[batch * 1024 + col], encf(v));
                }
            }
        return;
    }

#pragma unroll
    for (int mt = 0; mt < 4; mt++)
#pragma unroll
        for (int nt = 0; nt < 4; nt++) {
            int r = row0 + wr * 64 + mt * 16 + g;
            int c = col0 + wc * 32 + nt * 8 + 2 * t;
            float v0 = acc[mt][nt][0], v1 = acc[mt][nt][1];
            float v2 = acc[mt][nt][2], v3 = acc[mt][nt][3];
            if (mode == 1) {
                float sr0 = sqb[r & 1023], sr8 = sqb[(r + 8) & 1023];
                float sc0 = sqb[c & 1023], sc1 = sqb[(c + 1) & 1023];
                v0 = 2.f * v0 - sr0 - sc0; v1 = 2.f * v1 - sr0 - sc1;
                v2 = 2.f * v2 - sr8 - sc0; v3 = 2.f * v3 - sr8 - sc1;
            }
            *(float2*)&C[(size_t)r * ldc + c] = make_float2(v0, v1);
            *(float2*)&C[(size_t)(r + 8) * ldc + c] = make_float2(v2, v3);
            if (mode == 1 && bi != bj) {
                C[(size_t)c * ldc + r] = v0;
                C[(size_t)(c + 1) * ldc + r] = v1;
                C[(size_t)c * ldc + r + 8] = v2;
                C[(size_t)(c + 1) * ldc + r + 8] = v3;
            }
        }
}

// ---------------- 128x128x8 FFMA SGEMM (layer 0 only, K=3) -----------------
__global__ void __launch_bounds__(256, 2)
sgemm128(const float* __restrict__ A, int lda, long long sA,
         const float* __restrict__ B, int ldb, long long sB,
         const float* __restrict__ sq,
         float* __restrict__ C, int ldc, long long sC,
         int M, int N, int K, int mode)
{
    int bz = blockIdx.z;
    A += (long long)bz * sA;
    B += (long long)bz * sB;
    C += (long long)bz * sC;
    const float* sqb = sq ? (sq + (long long)bz * M) : nullptr;

    int bi, bj;
    if (mode == 1) {
        int nb = N >> 7;
        int p = blockIdx.x;
        bi = 0;
        while (p >= nb - bi) { p -= nb - bi; bi++; }
        bj = bi + p;
    } else { bi = blockIdx.x; bj = blockIdx.y; }
    const int row0 = bi * 128;
    const int col0 = bj * 128;

    __shared__ float As[2][8][132];
    __shared__ float Bs[2][8][132];

    const int tid = threadIdx.x;
    const int lk = tid & 7;
    const int lm = tid >> 3;
    const int tx = tid & 15;
    const int ty = tid >> 4;

    float acc[8][8];
#pragma unroll
    for (int i = 0; i < 8; i++)
#pragma unroll
        for (int j = 0; j < 8; j++) acc[i][j] = 0.f;

    float pa[4], pb[4];
    const int nk = (K + 7) >> 3;

    {
        int k = lk;
        bool ok = (k < K);
#pragma unroll
        for (int j = 0; j < 4; j++) {
            int m = lm + 32 * j;
            pa[j] = ok ? A[(long long)(row0 + m) * lda + k] : 0.f;
            pb[j] = ok ? B[(long long)(col0 + m) * ldb + k] : 0.f;
        }
#pragma unroll
        for (int j = 0; j < 4; j++) {
            As[0][lk][lm + 32 * j] = pa[j];
            Bs[0][lk][lm + 32 * j] = pb[j];
        }
    }
    __syncthreads();

    for (int t = 0; t < nk; t++) {
        int cur = t & 1;
        if (t + 1 < nk) {
            int k = (t + 1) * 8 + lk;
            bool ok = (k < K);
#pragma unroll
            for (int j = 0; j < 4; j++) {
                int m = lm + 32 * j;
                pa[j] = ok ? A[(long long)(row0 + m) * lda + k] : 0.f;
                pb[j] = ok ? B[(long long)(col0 + m) * ldb + k] : 0.f;
            }
        }
#pragma unroll
        for (int kk = 0; kk < 8; kk++) {
            float a[8], b[8];
            *(float4*)&a[0] = *(const float4*)&As[cur][kk][ty * 4];
            *(float4*)&a[4] = *(const float4*)&As[cur][kk][64 + ty * 4];
            *(float4*)&b[0] = *(const float4*)&Bs[cur][kk][tx * 4];
            *(float4*)&b[4] = *(const float4*)&Bs[cur][kk][64 + tx * 4];
#pragma unroll
            for (int i = 0; i < 8; i++)
#pragma unroll
                for (int j = 0; j < 8; j++)
                    acc[i][j] += a[i] * b[j];
        }
        if (t + 1 < nk) {
            int nxt = cur ^ 1;
#pragma unroll
            for (int j = 0; j < 4; j++) {
                As[nxt][lk][lm + 32 * j] = pa[j];
                Bs[nxt][lk][lm + 32 * j] = pb[j];
            }
        }
        __syncthreads();
    }

#pragma unroll
    for (int ih = 0; ih < 2; ih++) {
#pragma unroll
        for (int i = 0; i < 4; i++) {
            int r = row0 + ih * 64 + ty * 4 + i;
            float srow = (mode == 1) ? sqb[r] : 0.f;
#pragma unroll
            for (int jh = 0; jh < 2; jh++) {
                float outv[4];
#pragma unroll
                for (int j = 0; j < 4; j++) {
                    float v = acc[ih * 4 + i][jh * 4 + j];
                    if (mode == 1)
                        v = (2.f * v - srow) - sqb[col0 + jh * 64 + tx * 4 + j];
                    outv[j] = v;
                }
                *(float4*)&C[(long long)r * ldc + col0 + jh * 64 + tx * 4] =
                    *(float4*)&outv[0];
            }
        }
    }

    if (mode == 1 && bi != bj) {
#pragma unroll
        for (int jh = 0; jh < 2; jh++)
#pragma unroll
            for (int j = 0; j < 4; j++) {
                int c = col0 + jh * 64 + tx * 4 + j;
                float sc = sqb[c];
#pragma unroll
                for (int ih = 0; ih < 2; ih++) {
                    int rb = row0 + ih * 64 + ty * 4;
                    float mv[4];
#pragma unroll
                    for (int i = 0; i < 4; i++)
                        mv[i] = (2.f * acc[ih * 4 + i][jh * 4 + j] - sqb[rb + i]) - sc;
                    *(float4*)&C[(long long)c * ldc + rb] = *(float4*)&mv[0];
                }
            }
    }
}

// ---------------- squared norms ---------------------------------------------
__global__ void sq_kernel(const float* __restrict__ H, int lda, int C,
                          float* __restrict__ SQ)
{
    int gwarp = (blockIdx.x * blockDim.x + threadIdx.x) >> 5;
    int lane = threadIdx.x & 31;
    if (gwarp >= 16 * 1024) return;
    const float* h = H + (long long)gwarp * lda;
    float s = 0.f;
    for (int c = lane; c < C; c += 32) { float v = h[c]; s += v * v; }
#pragma unroll
    for (int d = 16; d > 0; d >>= 1) s += __shfl_down_sync(0xffffffffu, s, d);
    if (lane == 0) SQ[gwarp] = s;
}

// ---------------- top-40 via byte-wise radix select -------------------------
__global__ void __launch_bounds__(256)
topk40_kernel(const float* __restrict__ S, int* __restrict__ IDX)
{
    int row = blockIdx.x;
    const float* s = S + (long long)row * 1024;
    int tid = threadIdx.x;
    int lane = tid & 31, w = tid >> 5;

    unsigned key[4];
    {
        float4 v = ((const float4*)s)[tid];
        key[0] = encf(v.x); key[1] = encf(v.y);
        key[2] = encf(v.z); key[3] = encf(v.w);
    }
    bool cand[4] = {true, true, true, true};

    __shared__ unsigned hist[256];
    __shared__ unsigned cntge[256];
    __shared__ unsigned wsum[8];
    __shared__ int shB;
    __shared__ unsigned shGT;
    __shared__ int outcnt, tiecnt;
    __shared__ int tielist[1024];

    unsigned prefix = 0;
    int kneed = 40;
    unsigned T = 0;
    int r = 0;
    bool done = false;

    for (int level = 0; level < 4 && !done; level++) {
        const int shift = 24 - 8 * level;
        hist[tid] = 0;
        __syncthreads();
#pragma unroll
        for (int j = 0; j < 4; j++)
            if (cand[j]) atomicAdd(&hist[(key[j] >> shift) & 255u], 1u);
        __syncthreads();

        unsigned v = hist[255 - tid];
#pragma unroll
        for (int d = 1; d < 32; d <<= 1) {
            unsigned n = __shfl_up_sync(0xffffffffu, v, d);
            if (lane >= d) v += n;
        }
        if (lane == 31) wsum[w] = v;
        __syncthreads();
        if (tid == 0) {
            unsigned a = 0;
#pragma unroll
            for (int q = 0; q < 8; q++) { unsigned t2 = wsum[q]; wsum[q] = a; a += t2; }
        }
        __syncthreads();
        cntge[255 - tid] = v + wsum[w];
        __syncthreads();

        unsigned geb = cntge[tid];
        unsigned geb1 = (tid == 255) ? 0u : cntge[tid + 1];
        if (geb >= (unsigned)kneed && geb1 < (unsigned)kneed) {
            shB = tid;
            shGT = geb1;
        }
        __syncthreads();
        int B = shB;
        int gt = (int)shGT;
        int kn = kneed - gt;
        int hb = (int)hist[B];
        if (hb == kn) {
            T = (prefix | ((unsigned)B << shift)) - 1u;
            r = 0;
            done = true;
        } else if (shift == 0) {
            T = prefix | (unsigned)B;
            r = kn;
            done = true;
        } else {
            prefix |= (unsigned)B << shift;
            kneed = kn;
#pragma unroll
            for (int j = 0; j < 4; j++)
                cand[j] = cand[j] && (((key[j] >> shift) & 255u) == (unsigned)B);
        }
        __syncthreads();
    }

    if (tid == 0) { outcnt = 0; tiecnt = 0; }
    __syncthreads();

#pragma unroll
    for (int j = 0; j < 4; j++) {
        int m = tid * 4 + j;
        if (key[j] > T) {
            int slot = atomicAdd(&outcnt, 1);
            IDX[row * 40 + slot] = m;
        } else if (r > 0 && key[j] == T) {
            int t2 = atomicAdd(&tiecnt, 1);
            tielist[t2] = m;
        }
    }
    __syncthreads();

    if (r > 0) {
        int tt = tiecnt;
        for (int p = tid; p < tt; p += 256) {
            int mi = tielist[p];
            int rk = 0;
            for (int q = 0; q < tt; q++) rk += (tielist[q] < mi);
            if (rk < r) {
                int slot = atomicAdd(&outcnt, 1);
                IDX[row * 40 + slot] = mi;
            }
        }
    }
}

// ---------------- weight transform ------------------------------------------
__global__ void wprep_kernel(const float* __restrict__ W, float* __restrict__ WPQ,
                             int Co, int C)
{
    int i = blockIdx.x * blockDim.x + threadIdx.x;
    if (i >= Co * C) return;
    int o = i / C, c = i % C;
    float wl = W[o * 2 * C + c];
    float wr = W[o * 2 * C + C + c];
    WPQ[o * C + c] = wl;
    WPQ[(Co + o) * C + c] = wr - wl;
}

// ---------------- gather-max + BN affine + LeakyReLU ------------------------
__global__ void edge_gathermax(const float* __restrict__ PQ,
                               const int* __restrict__ IDX,
                               const float* __restrict__ g,
                               const float* __restrict__ bb,
                               float* __restrict__ OUT,
                               int Co, int ldo)
{
    const float BN_INV = 0.9999950000374997f;
    int pt = blockIdx.x;
    int b = pt >> 10;
    __shared__ int nb[40];
    if (threadIdx.x < 40) nb[threadIdx.x] = IDX[pt * 40 + threadIdx.x];
    __syncthreads();
    int ld = 2 * Co;
    long long bbase = (long long)(b << 10) * ld;
    for (int o = threadIdx.x; o < Co; o += blockDim.x) {
        float mx = -CUDART_INF_F, mn = CUDART_INF_F;
#pragma unroll 8
        for (int k = 0; k < 40; k++) {
            float v = PQ[bbase + (long long)nb[k] * ld + o];
            mx = fmaxf(mx, v);
            mn = fminf(mn, v);
        }
        float q  = PQ[(long long)pt * ld + Co + o];
        float gg = g[o];
        float y = (gg >= 0.f ? mx : mn) + q;
        y = gg * (y * BN_INV) + bb[o];
        y = y > 0.f ? y : 0.2f * y;
        OUT[(long long)pt * ldo + o] = y;
    }
}

// ---------------- gmax init / decode ----------------------------------------
__global__ void gmax_init(unsigned* __restrict__ g)
{
    g[blockIdx.x * 1024 + threadIdx.x] = 0u;
}

__global__ void decode_out(const unsigned* __restrict__ g,
                           const float* __restrict__ bf, float* __restrict__ out)
{
    int i = blockIdx.x * 256 + threadIdx.x;
    unsigned e = g[i];
    unsigned u = (e & 0x80000000u) ? (e ^ 0x80000000u) : ~e;
    out[i] = __uint_as_float(u) + bf[i & 1023];
}

// ---------------- launch -----------------------------------------------------
extern "C" void kernel_launch(void* const* d_in, const int* in_sizes, int n_in,
                              void* d_out, int out_size)
{
    (void)in_sizes; (void)n_in; (void)out_size;
    const float* x  = (const float*)d_in[0];
    const float* w[4]  = {(const float*)d_in[1], (const float*)d_in[4],
                          (const float*)d_in[7], (const float*)d_in[10]};
    const float* g[4]  = {(const float*)d_in[2], (const float*)d_in[5],
                          (const float*)d_in[8], (const float*)d_in[11]};
    const float* bb[4] = {(const float*)d_in[3], (const float*)d_in[6],
                          (const float*)d_in[9], (const float*)d_in[12]};
    const float* wf = (const float*)d_in[13];
    const float* bf = (const float*)d_in[14];
    float* out = (float*)d_out;

    float *dist, *sq, *pq, *cat, *wpq; int* idx; unsigned* gm;
    uint32_t *ah, *al, *wh, *wl, *fh, *fl, *chp, *clp;
    cudaGetSymbolAddress((void**)&dist, d_dist);
    cudaGetSymbolAddress((void**)&sq,   d_sq);
    cudaGetSymbolAddress((void**)&idx,  d_idx);
    cudaGetSymbolAddress((void**)&pq,   d_pq);
    cudaGetSymbolAddress((void**)&cat,  d_cat);
    cudaGetSymbolAddress((void**)&wpq,  d_wpq);
    cudaGetSymbolAddress((void**)&gm,   d_gmax);
    cudaGetSymbolAddress((void**)&ah,   d_ah);
    cudaGetSymbolAddress((void**)&al,   d_al);
    cudaGetSymbolAddress((void**)&wh,   d_wh);
    cudaGetSymbolAddress((void**)&wl,   d_wl);
    cudaGetSymbolAddress((void**)&fh,   d_fh);
    cudaGetSymbolAddress((void**)&fl,   d_fl);
    cudaGetSymbolAddress((void**)&chp,  d_ch);
    cudaGetSymbolAddress((void**)&clp,  d_cl);

    cudaFuncSetAttribute(hgemm, cudaFuncAttributeMaxDynamicSharedMemorySize,
                         HSMEM);

    const int Cs[4]    = {3, 64, 64, 128};
    const int Cos[4]   = {64, 64, 128, 256};
    const int offs[4]  = {0, 64, 128, 256};
    const int woff[4]  = {0, 1024, 9216, 25600};     // element offsets
    const int woffw[4] = {0, 512, 4608, 12800};      // word offsets

    // layer 0 (K=3: FFMA path)
    gmax_init<<<16, 1024>>>(gm);
    sq_kernel<<<2048, 256>>>(x, 3, 3, sq);
    sgemm128<<<dim3(36, 1, 16), 256>>>(
        x, 3, 1024LL * 3, x, 3, 1024LL * 3, sq,
        dist, 1024, 1024LL * 1024, 1024, 1024, 3, 1);
    topk40_kernel<<<16384, 256>>>(dist, idx);
    for (int l = 0; l < 4; l++)
        wprep_kernel<<<(Cos[l] * Cs[l] + 255) / 256, 256>>>(w[l], wpq + woff[l],
                                                            Cos[l], Cs[l]);
    cvt1d_h<<<(92160 / 4 + 255) / 256, 256>>>(wpq, wh, wl, 92160 / 4);
    cvt1d_h<<<(1024 * 512 / 4 + 255) / 256, 256>>>(wf, fh, fl, 1024 * 512 / 4);
    sgemm128<<<dim3(128, 1, 1), 256>>>(
        x, 3, 0, wpq, 3, 0, nullptr,
        pq, 128, 0, 16384, 128, 3, 0);
    edge_gathermax<<<16384, 64>>>(pq, idx, g[0], bb[0], cat + offs[0], 64, 512);

    // layers 1-3 on tensor cores (fp16x3)
    for (int l = 1; l < 4; l++) {
        int C = Cs[l], Co = Cos[l];
        const float* A = cat + offs[l - 1];
        int Cw = C >> 1;

        sq_kernel<<<2048, 256>>>(A, 512, C, sq);
        cvt2d_h<<<(16384 * C / 4 + 255) / 256, 256>>>(A, 512, C, ah, al);
        hgemm<<<dim3(36, 1, 16), 256, HSMEM>>>(
            ah, al, Cw, 1024LL * Cw, nullptr, nullptr, 0, sq,
            dist, 1024, 1024LL * 1024, 1024, C, 1, nullptr);
        topk40_kernel<<<16384, 256>>>(dist, idx);
        hgemm<<<dim3(128, (2 * Co) / 128, 1), 256, HSMEM>>>(
            ah, al, Cw, 0, wh + woffw[l], wl + woffw[l], Cw, nullptr,
            pq, 2 * Co, 0, 2 * Co, C, 0, nullptr);
        edge_gathermax<<<16384, Co>>>(pq, idx, g[l], bb[l], cat + offs[l], Co, 512);
    }

    // final linear 512 -> 1024 (fp16x3, fused max over N)
    cvt1d_h<<<(16384 * 512 / 4 + 255) / 256, 256>>>(cat, chp, clp, 16384 * 512 / 4);
    hgemm<<<dim3(128, 8, 1), 256, HSMEM>>>(
        chp, clp, 256, 0, fh, fl, 256, nullptr,
        dist, 0, 0, 1024, 512, 2, gm);
    decode_out<<<64, 256>>>(gm, bf, out);
}

// round 12
// speedup vs baseline: 2.8600x; 1.0954x over previous
#include <cuda_runtime.h>
#include <cuda_fp16.h>
#include <math_constants.h>
#include <cstdint>

// ---------------- scratch (static device globals; no allocation) ------------
__device__ float    d_dist[16 * 1024 * 1024];
__device__ float    d_sq  [16 * 1024];
__device__ int      d_idx [16 * 1024 * 40];
__device__ float    d_pq  [16 * 1024 * 512];
__device__ float    d_cat [16 * 1024 * 512];
__device__ float    d_wpq [92160];
__device__ unsigned d_gmax[16 * 1024];
// fp16-split planes (packed half2 words, k-pairs)
__device__ uint32_t d_ah[16 * 1024 * 64], d_al[16 * 1024 * 64];
__device__ uint32_t d_wh[46080],          d_wl[46080];
__device__ uint32_t d_fh[1024 * 256],     d_fl[1024 * 256];
__device__ uint32_t d_ch[16 * 1024 * 256], d_cl[16 * 1024 * 256];

static __device__ __forceinline__ unsigned encf(float v) {
    unsigned u = __float_as_uint(v);
    return (u & 0x80000000u) ? ~u : (u | 0x80000000u);
}
static __device__ __forceinline__ void hsplit2(float a, float b,
                                               uint32_t& h, uint32_t& l) {
    __half ha = __float2half_rn(a), hb = __float2half_rn(b);
    __half la = __float2half_rn(a - __half2float(ha));
    __half lb = __float2half_rn(b - __half2float(hb));
    __half2 H = __halves2half2(ha, hb), L = __halves2half2(la, lb);
    h = *(uint32_t*)&H;
    l = *(uint32_t*)&L;
}
static __device__ __forceinline__ void mma_f16(float* c, uint32_t a0, uint32_t a1,
                                               uint32_t a2, uint32_t a3,
                                               uint32_t b0, uint32_t b1) {
    asm volatile(
        "mma.sync.aligned.m16n8k16.row.col.f32.f16.f16.f32 "
        "{%0,%1,%2,%3}, {%4,%5,%6,%7}, {%8,%9}, {%0,%1,%2,%3};"
        : "+f"(c[0]), "+f"(c[1]), "+f"(c[2]), "+f"(c[3])
        : "r"(a0), "r"(a1), "r"(a2), "r"(a3), "r"(b0), "r"(b1));
}

static constexpr int KSW   = 128 * 12;
static constexpr int PLW   = 2 * KSW;
static constexpr int HSMEM = 4 * PLW * 4;   // 49152 bytes

// ---------------- conversion kernels ----------------------------------------
__global__ void cvt1d_h(const float* __restrict__ src, uint32_t* __restrict__ hi,
                        uint32_t* __restrict__ lo, int n4)
{
    int i = blockIdx.x * 256 + threadIdx.x;
    if (i >= n4) return;
    float4 v = ((const float4*)src)[i];
    uint2 h, l;
    hsplit2(v.x, v.y, h.x, l.x);
    hsplit2(v.z, v.w, h.y, l.y);
    ((uint2*)hi)[i] = h;
    ((uint2*)lo)[i] = l;
}

__global__ void cvt2d_h(const float* __restrict__ src, int ld, int cols,
                        uint32_t* __restrict__ hi, uint32_t* __restrict__ lo)
{
    int i = blockIdx.x * 256 + threadIdx.x;
    int c4s = cols >> 2;
    int r = i / c4s, c4 = i - r * c4s;
    if (r >= 16384) return;
    float4 v = *(const float4*)&src[(size_t)r * ld + c4 * 4];
    uint2 h, l;
    hsplit2(v.x, v.y, h.x, l.x);
    hsplit2(v.z, v.w, h.y, l.y);
    ((uint2*)hi)[r * (cols >> 2) + c4] = h;
    ((uint2*)lo)[r * (cols >> 2) + c4] = l;
}

// ============ fp16x3 tensor GEMM: C = A(..xK) * B(NxK)^T ====================
// mode 0: plain store.  mode 1: dist-symmetric (B=A, upper-tri, +mirror).
// mode 2: fused max over rows -> atomicMax(gmax).
__global__ void __launch_bounds__(256, 2)
hgemm(const uint32_t* __restrict__ Ah, const uint32_t* __restrict__ Al,
      int ldaw, long long sA,
      const uint32_t* __restrict__ Bh, const uint32_t* __restrict__ Bl,
      int ldbw,
      const float* __restrict__ sq,
      float* __restrict__ C, int ldc, long long sC,
      int N, int K, int mode, unsigned* __restrict__ gmax)
{
    extern __shared__ uint32_t dsm[];
    uint32_t* sAh = dsm;
    uint32_t* sAl = sAh + PLW;
    uint32_t* sBh = sAl + PLW;
    uint32_t* sBl = sBh + PLW;

    int bz = blockIdx.z;
    Ah += (long long)bz * sA;
    Al += (long long)bz * sA;
    const float* sqb = sq ? sq + (long long)bz * 1024 : nullptr;
    C += (long long)bz * sC;

    int bi, bj;
    if (mode == 1) {
        int nb = N >> 7;
        int p = blockIdx.x;
        bi = 0;
        while (p >= nb - bi) { p -= nb - bi; bi++; }
        bj = bi + p;
    } else { bi = blockIdx.x; bj = blockIdx.y; }
    const int row0 = bi * 128, col0 = bj * 128;

    const uint32_t* Bh2 = (mode == 1) ? Ah : Bh;
    const uint32_t* Bl2 = (mode == 1) ? Al : Bl;
    const int ldb2 = (mode == 1) ? ldaw : ldbw;

    const int tid = threadIdx.x;
    const int wid = tid >> 5, lane = tid & 31;
    const int wr = wid >> 2, wc = wid & 3;
    const int g = lane >> 2, t = lane & 3;

    float acc[4][4][4];
#pragma unroll
    for (int mt = 0; mt < 4; mt++)
#pragma unroll
        for (int nt = 0; nt < 4; nt++)
#pragma unroll
            for (int i = 0; i < 4; i++) acc[mt][nt][i] = 0.f;

    const int nch = K >> 5;
    for (int ch = 0; ch < nch; ch++) {
        const int k0w = ch * 16;
        __syncthreads();
#pragma unroll
        for (int i = 0; i < 2; i++) {
            int id4 = i * 256 + tid;
            int row = id4 >> 2;
            int w4 = id4 & 3;
            int ks = w4 >> 1, wi = (w4 & 1) * 4;
            size_t ga = (size_t)(row0 + row) * ldaw + k0w + w4 * 4;
            size_t gb = (size_t)(col0 + row) * ldb2 + k0w + w4 * 4;
            uint4 vah = *(const uint4*)&Ah[ga];
            uint4 val = *(const uint4*)&Al[ga];
            uint4 vbh = *(const uint4*)&Bh2[gb];
            uint4 vbl = *(const uint4*)&Bl2[gb];
            int so = ks * KSW + row * 12 + wi;
            *(uint4*)&sAh[so] = vah;
            *(uint4*)&sAl[so] = val;
            *(uint4*)&sBh[so] = vbh;
            *(uint4*)&sBl[so] = vbl;
        }
        __syncthreads();

#pragma unroll
        for (int ks = 0; ks < 2; ks++) {
            const uint32_t* pAh = sAh + ks * KSW;
            const uint32_t* pAl = sAl + ks * KSW;
            const uint32_t* pBh = sBh + ks * KSW;
            const uint32_t* pBl = sBl + ks * KSW;

            uint32_t bh0[4], bh1[4], bl0[4], bl1[4];
#pragma unroll
            for (int nt = 0; nt < 4; nt++) {
                int nb_ = wc * 32 + nt * 8 + g;
                bh0[nt] = pBh[nb_ * 12 + t];
                bh1[nt] = pBh[nb_ * 12 + 4 + t];
                bl0[nt] = pBl[nb_ * 12 + t];
                bl1[nt] = pBl[nb_ * 12 + 4 + t];
            }
            uint32_t a[4][4];
#pragma unroll
            for (int mt = 0; mt < 4; mt++) {
                int rb = wr * 64 + mt * 16 + g;
                a[mt][0] = pAh[rb * 12 + t];
                a[mt][1] = pAh[(rb + 8) * 12 + t];
                a[mt][2] = pAh[rb * 12 + 4 + t];
                a[mt][3] = pAh[(rb + 8) * 12 + 4 + t];
            }
#pragma unroll
            for (int nt = 0; nt < 4; nt++)
#pragma unroll
                for (int mt = 0; mt < 4; mt++) {
                    mma_f16(acc[mt][nt], a[mt][0], a[mt][1], a[mt][2], a[mt][3],
                            bh0[nt], bh1[nt]);
                    mma_f16(acc[mt][nt], a[mt][0], a[mt][1], a[mt][2], a[mt][3],
                            bl0[nt], bl1[nt]);
                }
#pragma unroll
            for (int mt = 0; mt < 4; mt++) {
                int rb = wr * 64 + mt * 16 + g;
                a[mt][0] = pAl[rb * 12 + t];
                a[mt][1] = pAl[(rb + 8) * 12 + t];
                a[mt][2] = pAl[rb * 12 + 4 + t];
                a[mt][3] = pAl[(rb + 8) * 12 + 4 + t];
            }
#pragma unroll
            for (int nt = 0; nt < 4; nt++)
#pragma unroll
                for (int mt = 0; mt < 4; mt++)
                    mma_f16(acc[mt][nt], a[mt][0], a[mt][1], a[mt][2], a[mt][3],
                            bh0[nt], bh1[nt]);
        }
    }

    if (mode == 2) {
        const int batch = row0 >> 10;
#pragma unroll
        for (int nt = 0; nt < 4; nt++)
#pragma unroll
            for (int j = 0; j < 2; j++) {
                float v = -CUDART_INF_F;
#pragma unroll
                for (int mt = 0; mt < 4; mt++)
                    v = fmaxf(v, fmaxf(acc[mt][nt][j], acc[mt][nt][j + 2]));
#pragma unroll
                for (int off = 4; off < 32; off <<= 1)
                    v = fmaxf(v, __shfl_xor_sync(0xffffffffu, v, off));
                if (lane < 4) {
                    int col = col0 + wc * 32 + nt * 8 + 2 * lane + j;
                    atomicMax(&gmax[batch * 1024 + col], encf(v));
                }
            }
        return;
    }

#pragma unroll
    for (int mt = 0; mt < 4; mt++)
#pragma unroll
        for (int nt = 0; nt < 4; nt++) {
            int r = row0 + wr * 64 + mt * 16 + g;
            int c = col0 + wc * 32 + nt * 8 + 2 * t;
            float v0 = acc[mt][nt][0], v1 = acc[mt][nt][1];
            float v2 = acc[mt][nt][2], v3 = acc[mt][nt][3];
            if (mode == 1) {
                float sr0 = sqb[r & 1023], sr8 = sqb[(r + 8) & 1023];
                float sc0 = sqb[c & 1023], sc1 = sqb[(c + 1) & 1023];
                v0 = 2.f * v0 - sr0 - sc0; v1 = 2.f * v1 - sr0 - sc1;
                v2 = 2.f * v2 - sr8 - sc0; v3 = 2.f * v3 - sr8 - sc1;
            }
            *(float2*)&C[(size_t)r * ldc + c] = make_float2(v0, v1);
            *(float2*)&C[(size_t)(r + 8) * ldc + c] = make_float2(v2, v3);
            if (mode == 1 && bi != bj) {
                C[(size_t)c * ldc + r] = v0;
                C[(size_t)(c + 1) * ldc + r] = v1;
                C[(size_t)c * ldc + r + 8] = v2;
                C[(size_t)(c + 1) * ldc + r + 8] = v3;
            }
        }
}

// ---------------- 128x128x8 FFMA SGEMM (layer 0 only, K=3) -----------------
__global__ void __launch_bounds__(256, 2)
sgemm128(const float* __restrict__ A, int lda, long long sA,
         const float* __restrict__ B, int ldb, long long sB,
         const float* __restrict__ sq,
         float* __restrict__ C, int ldc, long long sC,
         int M, int N, int K, int mode)
{
    int bz = blockIdx.z;
    A += (long long)bz * sA;
    B += (long long)bz * sB;
    C += (long long)bz * sC;
    const float* sqb = sq ? (sq + (long long)bz * M) : nullptr;

    int bi, bj;
    if (mode == 1) {
        int nb = N >> 7;
        int p = blockIdx.x;
        bi = 0;
        while (p >= nb - bi) { p -= nb - bi; bi++; }
        bj = bi + p;
    } else { bi = blockIdx.x; bj = blockIdx.y; }
    const int row0 = bi * 128;
    const int col0 = bj * 128;

    __shared__ float As[2][8][132];
    __shared__ float Bs[2][8][132];

    const int tid = threadIdx.x;
    const int lk = tid & 7;
    const int lm = tid >> 3;
    const int tx = tid & 15;
    const int ty = tid >> 4;

    float acc[8][8];
#pragma unroll
    for (int i = 0; i < 8; i++)
#pragma unroll
        for (int j = 0; j < 8; j++) acc[i][j] = 0.f;

    float pa[4], pb[4];
    const int nk = (K + 7) >> 3;

    {
        int k = lk;
        bool ok = (k < K);
#pragma unroll
        for (int j = 0; j < 4; j++) {
            int m = lm + 32 * j;
            pa[j] = ok ? A[(long long)(row0 + m) * lda + k] : 0.f;
            pb[j] = ok ? B[(long long)(col0 + m) * ldb + k] : 0.f;
        }
#pragma unroll
        for (int j = 0; j < 4; j++) {
            As[0][lk][lm + 32 * j] = pa[j];
            Bs[0][lk][lm + 32 * j] = pb[j];
        }
    }
    __syncthreads();

    for (int t = 0; t < nk; t++) {
        int cur = t & 1;
        if (t + 1 < nk) {
            int k = (t + 1) * 8 + lk;
            bool ok = (k < K);
#pragma unroll
            for (int j = 0; j < 4; j++) {
                int m = lm + 32 * j;
                pa[j] = ok ? A[(long long)(row0 + m) * lda + k] : 0.f;
                pb[j] = ok ? B[(long long)(col0 + m) * ldb + k] : 0.f;
            }
        }
#pragma unroll
        for (int kk = 0; kk < 8; kk++) {
            float a[8], b[8];
            *(float4*)&a[0] = *(const float4*)&As[cur][kk][ty * 4];
            *(float4*)&a[4] = *(const float4*)&As[cur][kk][64 + ty * 4];
            *(float4*)&b[0] = *(const float4*)&Bs[cur][kk][tx * 4];
            *(float4*)&b[4] = *(const float4*)&Bs[cur][kk][64 + tx * 4];
#pragma unroll
            for (int i = 0; i < 8; i++)
#pragma unroll
                for (int j = 0; j < 8; j++)
                    acc[i][j] += a[i] * b[j];
        }
        if (t + 1 < nk) {
            int nxt = cur ^ 1;
#pragma unroll
            for (int j = 0; j < 4; j++) {
                As[nxt][lk][lm + 32 * j] = pa[j];
                Bs[nxt][lk][lm + 32 * j] = pb[j];
            }
        }
        __syncthreads();
    }

#pragma unroll
    for (int ih = 0; ih < 2; ih++) {
#pragma unroll
        for (int i = 0; i < 4; i++) {
            int r = row0 + ih * 64 + ty * 4 + i;
            float srow = (mode == 1) ? sqb[r] : 0.f;
#pragma unroll
            for (int jh = 0; jh < 2; jh++) {
                float outv[4];
#pragma unroll
                for (int j = 0; j < 4; j++) {
                    float v = acc[ih * 4 + i][jh * 4 + j];
                    if (mode == 1)
                        v = (2.f * v - srow) - sqb[col0 + jh * 64 + tx * 4 + j];
                    outv[j] = v;
                }
                *(float4*)&C[(long long)r * ldc + col0 + jh * 64 + tx * 4] =
                    *(float4*)&outv[0];
            }
        }
    }

    if (mode == 1 && bi != bj) {
#pragma unroll
        for (int jh = 0; jh < 2; jh++)
#pragma unroll
            for (int j = 0; j < 4; j++) {
                int c = col0 + jh * 64 + tx * 4 + j;
                float sc = sqb[c];
#pragma unroll
                for (int ih = 0; ih < 2; ih++) {
                    int rb = row0 + ih * 64 + ty * 4;
                    float mv[4];
#pragma unroll
                    for (int i = 0; i < 4; i++)
                        mv[i] = (2.f * acc[ih * 4 + i][jh * 4 + j] - sqb[rb + i]) - sc;
                    *(float4*)&C[(long long)c * ldc + rb] = *(float4*)&mv[0];
                }
            }
    }
}

// ---------------- squared norms ---------------------------------------------
__global__ void sq_kernel(const float* __restrict__ H, int lda, int C,
                          float* __restrict__ SQ)
{
    int gwarp = (blockIdx.x * blockDim.x + threadIdx.x) >> 5;
    int lane = threadIdx.x & 31;
    if (gwarp >= 16 * 1024) return;
    const float* h = H + (long long)gwarp * lda;
    float s = 0.f;
    for (int c = lane; c < C; c += 32) { float v = h[c]; s += v * v; }
#pragma unroll
    for (int d = 16; d > 0; d >>= 1) s += __shfl_down_sync(0xffffffffu, s, d);
    if (lane == 0) SQ[gwarp] = s;
}

// ---------------- top-40: radix levels with early brute-force exit ----------
// Emits the exact top-40 set (lax.top_k tie semantics: key desc, index asc).
__global__ void __launch_bounds__(256)
topk40_kernel(const float* __restrict__ S, int* __restrict__ IDX)
{
    int row = blockIdx.x;
    const float* s = S + (long long)row * 1024;
    int tid = threadIdx.x;
    int lane = tid & 31, w = tid >> 5;

    unsigned key[4];
    {
        float4 v = ((const float4*)s)[tid];
        key[0] = encf(v.x); key[1] = encf(v.y);
        key[2] = encf(v.z); key[3] = encf(v.w);
    }
    bool cand[4] = {true, true, true, true};

    __shared__ unsigned hist[256];
    __shared__ unsigned cntge[256];
    __shared__ unsigned wsum[8];
    __shared__ int shB;
    __shared__ unsigned shGT;
    __shared__ int outcnt, tiecnt;
    __shared__ unsigned long long tlist[1024];

    unsigned prefix = 0;
    int kneed = 40;
    unsigned lo = 0, hi = 0;
    int kn = 0;
    int fin = 0;          // 0=not done, 1=simple threshold, 2=brute force

    for (int level = 0; level < 4 && !fin; level++) {
        const int shift = 24 - 8 * level;
        hist[tid] = 0;
        __syncthreads();
#pragma unroll
        for (int j = 0; j < 4; j++)
            if (cand[j]) atomicAdd(&hist[(key[j] >> shift) & 255u], 1u);
        __syncthreads();

        unsigned v = hist[255 - tid];
#pragma unroll
        for (int d = 1; d < 32; d <<= 1) {
            unsigned n = __shfl_up_sync(0xffffffffu, v, d);
            if (lane >= d) v += n;
        }
        if (lane == 31) wsum[w] = v;
        __syncthreads();
        if (tid == 0) {
            unsigned a = 0;
#pragma unroll
            for (int q = 0; q < 8; q++) { unsigned t2 = wsum[q]; wsum[q] = a; a += t2; }
        }
        __syncthreads();
        cntge[255 - tid] = v + wsum[w];
        __syncthreads();

        unsigned geb = cntge[tid];
        unsigned geb1 = (tid == 255) ? 0u : cntge[tid + 1];
        if (geb >= (unsigned)kneed && geb1 < (unsigned)kneed) {
            shB = tid;
            shGT = geb1;
        }
        __syncthreads();
        int B = shB;
        int gt = (int)shGT;
        kn = kneed - gt;
        int hb = (int)hist[B];
        lo = prefix | ((unsigned)B << shift);
        hi = lo + ((shift < 32) ? ((1u << shift) - 1u) : 0u);
        if (hb == kn) {
            fin = 1;                               // all of bucket B included
        } else if (hb <= 96 || shift == 0) {
            fin = 2;                               // brute-force within bucket
        } else {
            prefix = lo;
            kneed = kn;
#pragma unroll
            for (int j = 0; j < 4; j++)
                cand[j] = cand[j] && (((key[j] >> shift) & 255u) == (unsigned)B);
        }
        __syncthreads();
    }

    if (tid == 0) { outcnt = 0; tiecnt = 0; }
    __syncthreads();

    if (fin == 1) {
        unsigned T = lo - 1u;                      // include whole bucket
#pragma unroll
        for (int j = 0; j < 4; j++) {
            if (key[j] > T) {
                int slot = atomicAdd(&outcnt, 1);
                IDX[row * 40 + slot] = tid * 4 + j;
            }
        }
        return;
    }

    // brute force: emit key > hi directly; rank in-bucket candidates
#pragma unroll
    for (int j = 0; j < 4; j++) {
        int m = tid * 4 + j;
        unsigned k2 = key[j];
        if (k2 > hi) {
            int slot = atomicAdd(&outcnt, 1);
            IDX[row * 40 + slot] = m;
        } else if (k2 >= lo) {
            int t2 = atomicAdd(&tiecnt, 1);
            tlist[t2] = ((unsigned long long)k2 << 32) | (unsigned)(2047 - m);
        }
    }
    __syncthreads();

    int tt = tiecnt;
    for (int p = tid; p < tt; p += 256) {
        unsigned long long me = tlist[p];
        int rk = 0;
        for (int q = 0; q < tt; q++) rk += (tlist[q] > me);
        if (rk < kn) {
            int slot = atomicAdd(&outcnt, 1);
            IDX[row * 40 + slot] = 2047 - (int)(me & 0xFFFFFFFFull);
        }
    }
}

// ---------------- weight transform ------------------------------------------
__global__ void wprep_kernel(const float* __restrict__ W, float* __restrict__ WPQ,
                             int Co, int C)
{
    int i = blockIdx.x * blockDim.x + threadIdx.x;
    if (i >= Co * C) return;
    int o = i / C, c = i % C;
    float wl = W[o * 2 * C + c];
    float wr = W[o * 2 * C + C + c];
    WPQ[o * C + c] = wl;
    WPQ[(Co + o) * C + c] = wr - wl;
}

// ---------------- gather-max (float4, multi-point blocks) -------------------
// blockDim = 128; G = 512/Co points per block; thread owns one float4 group.
__global__ void __launch_bounds__(128)
edge_gathermax(const float* __restrict__ PQ,
               const int* __restrict__ IDX,
               const float* __restrict__ g,
               const float* __restrict__ bb,
               float* __restrict__ OUT,
               int Co, int ldo)
{
    const float BN_INV = 0.9999950000374997f;
    const int c4n = Co >> 2;
    const int G = 128 / c4n;
    const int pbase = blockIdx.x * G;

    __shared__ int nb[8 * 40];
    for (int i = threadIdx.x; i < G * 40; i += 128)
        nb[i] = IDX[(pbase + i / 40) * 40 + (i % 40)];
    __syncthreads();

    const int p = threadIdx.x / c4n;
    const int o = (threadIdx.x - p * c4n) * 4;
    const int pt = pbase + p;
    const int b = pt >> 10;
    const int ld = 2 * Co;
    const float* base = PQ + (size_t)(b << 10) * ld + o;
    const int* nbp = nb + p * 40;

    float4 mx = make_float4(-CUDART_INF_F, -CUDART_INF_F, -CUDART_INF_F, -CUDART_INF_F);
    float4 mn = make_float4(CUDART_INF_F, CUDART_INF_F, CUDART_INF_F, CUDART_INF_F);
#pragma unroll 8
    for (int k = 0; k < 40; k++) {
        float4 v = *(const float4*)(base + (size_t)nbp[k] * ld);
        mx.x = fmaxf(mx.x, v.x); mn.x = fminf(mn.x, v.x);
        mx.y = fmaxf(mx.y, v.y); mn.y = fminf(mn.y, v.y);
        mx.z = fmaxf(mx.z, v.z); mn.z = fminf(mn.z, v.z);
        mx.w = fmaxf(mx.w, v.w); mn.w = fminf(mn.w, v.w);
    }
    float4 q  = *(const float4*)&PQ[(size_t)pt * ld + Co + o];
    float4 gg = *(const float4*)&g[o];
    float4 bv = *(const float4*)&bb[o];

    float4 y;
    y.x = (gg.x >= 0.f ? mx.x : mn.x) + q.x;
    y.y = (gg.y >= 0.f ? mx.y : mn.y) + q.y;
    y.z = (gg.z >= 0.f ? mx.z : mn.z) + q.z;
    y.w = (gg.w >= 0.f ? mx.w : mn.w) + q.w;
    y.x = gg.x * (y.x * BN_INV) + bv.x;
    y.y = gg.y * (y.y * BN_INV) + bv.y;
    y.z = gg.z * (y.z * BN_INV) + bv.z;
    y.w = gg.w * (y.w * BN_INV) + bv.w;
    y.x = y.x > 0.f ? y.x : 0.2f * y.x;
    y.y = y.y > 0.f ? y.y : 0.2f * y.y;
    y.z = y.z > 0.f ? y.z : 0.2f * y.z;
    y.w = y.w > 0.f ? y.w : 0.2f * y.w;

    *(float4*)&OUT[(size_t)pt * ldo + o] = y;
}

// ---------------- gmax init / decode ----------------------------------------
__global__ void gmax_init(unsigned* __restrict__ g)
{
    g[blockIdx.x * 1024 + threadIdx.x] = 0u;
}

__global__ void decode_out(const unsigned* __restrict__ g,
                           const float* __restrict__ bf, float* __restrict__ out)
{
    int i = blockIdx.x * 256 + threadIdx.x;
    unsigned e = g[i];
    unsigned u = (e & 0x80000000u) ? (e ^ 0x80000000u) : ~e;
    out[i] = __uint_as_float(u) + bf[i & 1023];
}

// ---------------- launch -----------------------------------------------------
extern "C" void kernel_launch(void* const* d_in, const int* in_sizes, int n_in,
                              void* d_out, int out_size)
{
    (void)in_sizes; (void)n_in; (void)out_size;
    const float* x  = (const float*)d_in[0];
    const float* w[4]  = {(const float*)d_in[1], (const float*)d_in[4],
                          (const float*)d_in[7], (const float*)d_in[10]};
    const float* g[4]  = {(const float*)d_in[2], (const float*)d_in[5],
                          (const float*)d_in[8], (const float*)d_in[11]};
    const float* bb[4] = {(const float*)d_in[3], (const float*)d_in[6],
                          (const float*)d_in[9], (const float*)d_in[12]};
    const float* wf = (const float*)d_in[13];
    const float* bf = (const float*)d_in[14];
    float* out = (float*)d_out;

    float *dist, *sq, *pq, *cat, *wpq; int* idx; unsigned* gm;
    uint32_t *ah, *al, *wh, *wl, *fh, *fl, *chp, *clp;
    cudaGetSymbolAddress((void**)&dist, d_dist);
    cudaGetSymbolAddress((void**)&sq,   d_sq);
    cudaGetSymbolAddress((void**)&idx,  d_idx);
    cudaGetSymbolAddress((void**)&pq,   d_pq);
    cudaGetSymbolAddress((void**)&cat,  d_cat);
    cudaGetSymbolAddress((void**)&wpq,  d_wpq);
    cudaGetSymbolAddress((void**)&gm,   d_gmax);
    cudaGetSymbolAddress((void**)&ah,   d_ah);
    cudaGetSymbolAddress((void**)&al,   d_al);
    cudaGetSymbolAddress((void**)&wh,   d_wh);
    cudaGetSymbolAddress((void**)&wl,   d_wl);
    cudaGetSymbolAddress((void**)&fh,   d_fh);
    cudaGetSymbolAddress((void**)&fl,   d_fl);
    cudaGetSymbolAddress((void**)&chp,  d_ch);
    cudaGetSymbolAddress((void**)&clp,  d_cl);

    cudaFuncSetAttribute(hgemm, cudaFuncAttributeMaxDynamicSharedMemorySize,
                         HSMEM);

    const int Cs[4]    = {3, 64, 64, 128};
    const int Cos[4]   = {64, 64, 128, 256};
    const int offs[4]  = {0, 64, 128, 256};
    const int woff[4]  = {0, 1024, 9216, 25600};
    const int woffw[4] = {0, 512, 4608, 12800};

    // layer 0 (K=3: FFMA path); launch #4 = topk l0 (profiled slot)
    gmax_init<<<16, 1024>>>(gm);
    sq_kernel<<<2048, 256>>>(x, 3, 3, sq);
    sgemm128<<<dim3(36, 1, 16), 256>>>(
        x, 3, 1024LL * 3, x, 3, 1024LL * 3, sq,
        dist, 1024, 1024LL * 1024, 1024, 1024, 3, 1);
    topk40_kernel<<<16384, 256>>>(dist, idx);
    for (int l = 0; l < 4; l++)
        wprep_kernel<<<(Cos[l] * Cs[l] + 255) / 256, 256>>>(w[l], wpq + woff[l],
                                                            Cos[l], Cs[l]);
    cvt1d_h<<<(92160 / 4 + 255) / 256, 256>>>(wpq, wh, wl, 92160 / 4);
    cvt1d_h<<<(1024 * 512 / 4 + 255) / 256, 256>>>(wf, fh, fl, 1024 * 512 / 4);
    sgemm128<<<dim3(128, 1, 1), 256>>>(
        x, 3, 0, wpq, 3, 0, nullptr,
        pq, 128, 0, 16384, 128, 3, 0);
    edge_gathermax<<<2048, 128>>>(pq, idx, g[0], bb[0], cat + offs[0], 64, 512);

    // layers 1-3 on tensor cores (fp16x3)
    for (int l = 1; l < 4; l++) {
        int C = Cs[l], Co = Cos[l];
        const float* A = cat + offs[l - 1];
        int Cw = C >> 1;

        sq_kernel<<<2048, 256>>>(A, 512, C, sq);
        cvt2d_h<<<(16384 * C / 4 + 255) / 256, 256>>>(A, 512, C, ah, al);
        hgemm<<<dim3(36, 1, 16), 256, HSMEM>>>(
            ah, al, Cw, 1024LL * Cw, nullptr, nullptr, 0, sq,
            dist, 1024, 1024LL * 1024, 1024, C, 1, nullptr);
        topk40_kernel<<<16384, 256>>>(dist, idx);
        hgemm<<<dim3(128, (2 * Co) / 128, 1), 256, HSMEM>>>(
            ah, al, Cw, 0, wh + woffw[l], wl + woffw[l], Cw, nullptr,
            pq, 2 * Co, 0, 2 * Co, C, 0, nullptr);
        edge_gathermax<<<16384 * Co / 512, 128>>>(pq, idx, g[l], bb[l],
                                                  cat + offs[l], Co, 512);
    }

    // final linear 512 -> 1024 (fp16x3, fused max over N)
    cvt1d_h<<<(16384 * 512 / 4 + 255) / 256, 256>>>(cat, chp, clp, 16384 * 512 / 4);
    hgemm<<<dim3(128, 8, 1), 256, HSMEM>>>(
        chp, clp, 256, 0, fh, fl, 256, nullptr,
        dist, 0, 0, 1024, 512, 2, gm);
    decode_out<<<64, 256>>>(gm, bf, out);
}

// round 14
// speedup vs baseline: 2.9940x; 1.0469x over previous
#include <cuda_runtime.h>
#include <cuda_fp16.h>
#include <math_constants.h>
#include <cstdint>

// ---------------- scratch (static device globals; no allocation) ------------
__device__ float    d_dist[16 * 1024 * 1024];
__device__ float    d_sq  [16 * 1024];
__device__ int      d_idx [16 * 1024 * 40];
__device__ float    d_pq  [16 * 1024 * 512];
__device__ float    d_wpq [92160];
__device__ unsigned d_gmax[16 * 1024];
// fp16-split planes (packed half2 words, k-pairs)
__device__ uint32_t d_ah[16 * 1024 * 64], d_al[16 * 1024 * 64];   // layer input (C<=128)
__device__ uint32_t d_wh[46080],          d_wl[46080];            // wpq
__device__ uint32_t d_fh[1024 * 256],     d_fl[1024 * 256];       // wf
__device__ uint32_t d_ch[16 * 1024 * 256], d_cl[16 * 1024 * 256]; // full cat

static __device__ __forceinline__ unsigned encf(float v) {
    unsigned u = __float_as_uint(v);
    return (u & 0x80000000u) ? ~u : (u | 0x80000000u);
}
static __device__ __forceinline__ void hsplit2(float a, float b,
                                               uint32_t& h, uint32_t& l) {
    __half ha = __float2half_rn(a), hb = __float2half_rn(b);
    __half la = __float2half_rn(a - __half2float(ha));
    __half lb = __float2half_rn(b - __half2float(hb));
    __half2 H = __halves2half2(ha, hb), L = __halves2half2(la, lb);
    h = *(uint32_t*)&H;
    l = *(uint32_t*)&L;
}
static __device__ __forceinline__ void mma_f16(float* c, uint32_t a0, uint32_t a1,
                                               uint32_t a2, uint32_t a3,
                                               uint32_t b0, uint32_t b1) {
    asm volatile(
        "mma.sync.aligned.m16n8k16.row.col.f32.f16.f16.f32 "
        "{%0,%1,%2,%3}, {%4,%5,%6,%7}, {%8,%9}, {%0,%1,%2,%3};"
        : "+f"(c[0]), "+f"(c[1]), "+f"(c[2]), "+f"(c[3])
        : "r"(a0), "r"(a1), "r"(a2), "r"(a3), "r"(b0), "r"(b1));
}

static constexpr int KSW   = 128 * 12;
static constexpr int PLW   = 2 * KSW;
static constexpr int HSMEM = 4 * PLW * 4;   // 49152 bytes

// ---------------- weight conversion ------------------------------------------
__global__ void cvt1d_h(const float* __restrict__ src, uint32_t* __restrict__ hi,
                        uint32_t* __restrict__ lo, int n4)
{
    int i = blockIdx.x * 256 + threadIdx.x;
    if (i >= n4) return;
    float4 v = ((const float4*)src)[i];
    uint2 h, l;
    hsplit2(v.x, v.y, h.x, l.x);
    hsplit2(v.z, v.w, h.y, l.y);
    ((uint2*)hi)[i] = h;
    ((uint2*)lo)[i] = l;
}

// ============ fp16x3 tensor GEMM: C = A(..xK) * B(NxK)^T ====================
// mode 0: plain store.  mode 1: dist-symmetric (B=A, upper-tri, +mirror).
// mode 2: fused max over rows -> atomicMax(gmax).
// Register-prefetch pipelined: next chunk's global loads overlap with mma.
__global__ void __launch_bounds__(256, 2)
hgemm(const uint32_t* __restrict__ Ah, const uint32_t* __restrict__ Al,
      int ldaw, long long sA,
      const uint32_t* __restrict__ Bh, const uint32_t* __restrict__ Bl,
      int ldbw,
      const float* __restrict__ sq,
      float* __restrict__ C, int ldc, long long sC,
      int N, int K, int mode, unsigned* __restrict__ gmax)
{
    extern __shared__ uint32_t dsm[];
    uint32_t* sAh = dsm;
    uint32_t* sAl = sAh + PLW;
    uint32_t* sBh = sAl + PLW;
    uint32_t* sBl = sBh + PLW;

    int bz = blockIdx.z;
    Ah += (long long)bz * sA;
    Al += (long long)bz * sA;
    const float* sqb = sq ? sq + (long long)bz * 1024 : nullptr;
    C += (long long)bz * sC;

    int bi, bj;
    if (mode == 1) {
        int nb = N >> 7;
        int p = blockIdx.x;
        bi = 0;
        while (p >= nb - bi) { p -= nb - bi; bi++; }
        bj = bi + p;
    } else { bi = blockIdx.x; bj = blockIdx.y; }
    const int row0 = bi * 128, col0 = bj * 128;

    const uint32_t* Bh2 = (mode == 1) ? Ah : Bh;
    const uint32_t* Bl2 = (mode == 1) ? Al : Bl;
    const int ldb2 = (mode == 1) ? ldaw : ldbw;

    const int tid = threadIdx.x;
    const int wid = tid >> 5, lane = tid & 31;
    const int wr = wid >> 2, wc = wid & 3;
    const int g = lane >> 2, t = lane & 3;

    float acc[4][4][4];
#pragma unroll
    for (int mt = 0; mt < 4; mt++)
#pragma unroll
        for (int nt = 0; nt < 4; nt++)
#pragma unroll
            for (int i = 0; i < 4; i++) acc[mt][nt][i] = 0.f;

    int lrow[2], lw4[2], lso[2];
    size_t loa[2], lob[2];
#pragma unroll
    for (int i = 0; i < 2; i++) {
        int id4 = i * 256 + tid;
        lrow[i] = id4 >> 2;
        lw4[i] = id4 & 3;
        int ks = lw4[i] >> 1, wi = (lw4[i] & 1) * 4;
        lso[i] = ks * KSW + lrow[i] * 12 + wi;
        loa[i] = (size_t)(row0 + lrow[i]) * ldaw + lw4[i] * 4;
        lob[i] = (size_t)(col0 + lrow[i]) * ldb2 + lw4[i] * 4;
    }

    uint4 pah[2], pal[2], pbh[2], pbl[2];
    const int nch = K >> 5;

#pragma unroll
    for (int i = 0; i < 2; i++) {
        pah[i] = *(const uint4*)&Ah[loa[i]];
        pal[i] = *(const uint4*)&Al[loa[i]];
        pbh[i] = *(const uint4*)&Bh2[lob[i]];
        pbl[i] = *(const uint4*)&Bl2[lob[i]];
    }
#pragma unroll
    for (int i = 0; i < 2; i++) {
        *(uint4*)&sAh[lso[i]] = pah[i];
        *(uint4*)&sAl[lso[i]] = pal[i];
        *(uint4*)&sBh[lso[i]] = pbh[i];
        *(uint4*)&sBl[lso[i]] = pbl[i];
    }
    __syncthreads();

    for (int ch = 0; ch < nch; ch++) {
        if (ch + 1 < nch) {
            const int k1 = (ch + 1) * 16;
#pragma unroll
            for (int i = 0; i < 2; i++) {
                pah[i] = *(const uint4*)&Ah[loa[i] + k1];
                pal[i] = *(const uint4*)&Al[loa[i] + k1];
                pbh[i] = *(const uint4*)&Bh2[lob[i] + k1];
                pbl[i] = *(const uint4*)&Bl2[lob[i] + k1];
            }
        }

#pragma unroll
        for (int ks = 0; ks < 2; ks++) {
            const uint32_t* pAh = sAh + ks * KSW;
            const uint32_t* pAl = sAl + ks * KSW;
            const uint32_t* pBh = sBh + ks * KSW;
            const uint32_t* pBl = sBl + ks * KSW;

            uint32_t bh0[4], bh1[4], bl0[4], bl1[4];
#pragma unroll
            for (int nt = 0; nt < 4; nt++) {
                int nb_ = wc * 32 + nt * 8 + g;
                bh0[nt] = pBh[nb_ * 12 + t];
                bh1[nt] = pBh[nb_ * 12 + 4 + t];
                bl0[nt] = pBl[nb_ * 12 + t];
                bl1[nt] = pBl[nb_ * 12 + 4 + t];
            }
            uint32_t a[4][4];
#pragma unroll
            for (int mt = 0; mt < 4; mt++) {
                int rb = wr * 64 + mt * 16 + g;
                a[mt][0] = pAh[rb * 12 + t];
                a[mt][1] = pAh[(rb + 8) * 12 + t];
                a[mt][2] = pAh[rb * 12 + 4 + t];
                a[mt][3] = pAh[(rb + 8) * 12 + 4 + t];
            }
#pragma unroll
            for (int nt = 0; nt < 4; nt++)
#pragma unroll
                for (int mt = 0; mt < 4; mt++) {
                    mma_f16(acc[mt][nt], a[mt][0], a[mt][1], a[mt][2], a[mt][3],
                            bh0[nt], bh1[nt]);
                    mma_f16(acc[mt][nt], a[mt][0], a[mt][1], a[mt][2], a[mt][3],
                            bl0[nt], bl1[nt]);
                }
#pragma unroll
            for (int mt = 0; mt < 4; mt++) {
                int rb = wr * 64 + mt * 16 + g;
                a[mt][0] = pAl[rb * 12 + t];
                a[mt][1] = pAl[(rb + 8) * 12 + t];
                a[mt][2] = pAl[rb * 12 + 4 + t];
                a[mt][3] = pAl[(rb + 8) * 12 + 4 + t];
            }
#pragma unroll
            for (int nt = 0; nt < 4; nt++)
#pragma unroll
                for (int mt = 0; mt < 4; mt++)
                    mma_f16(acc[mt][nt], a[mt][0], a[mt][1], a[mt][2], a[mt][3],
                            bh0[nt], bh1[nt]);
        }
        __syncthreads();
        if (ch + 1 < nch) {
#pragma unroll
            for (int i = 0; i < 2; i++) {
                *(uint4*)&sAh[lso[i]] = pah[i];
                *(uint4*)&sAl[lso[i]] = pal[i];
                *(uint4*)&sBh[lso[i]] = pbh[i];
                *(uint4*)&sBl[lso[i]] = pbl[i];
            }
            __syncthreads();
        }
    }

    if (mode == 2) {
        const int batch = row0 >> 10;
#pragma unroll
        for (int nt = 0; nt < 4; nt++)
#pragma unroll
            for (int j = 0; j < 2; j++) {
                float v = -CUDART_INF_F;
#pragma unroll
                for (int mt = 0; mt < 4; mt++)
                    v = fmaxf(v, fmaxf(acc[mt][nt][j], acc[mt][nt][j + 2]));
#pragma unroll
                for (int off = 4; off < 32; off <<= 1)
                    v = fmaxf(v, __shfl_xor_sync(0xffffffffu, v, off));
                if (lane < 4) {
                    int col = col0 + wc * 32 + nt * 8 + 2 * lane + j;
                    atomicMax(&gmax[batch * 1024 + col], encf(v));
                }
            }
        return;
    }

#pragma unroll
    for (int mt = 0; mt < 4; mt++)
#pragma unroll
        for (int nt = 0; nt < 4; nt++) {
            int r = row0 + wr * 64 + mt * 16 + g;
            int c = col0 + wc * 32 + nt * 8 + 2 * t;
            float v0 = acc[mt][nt][0], v1 = acc[mt][nt][1];
            float v2 = acc[mt][nt][2], v3 = acc[mt][nt][3];
            if (mode == 1) {
                float sr0 = sqb[r & 1023], sr8 = sqb[(r + 8) & 1023];
                float sc0 = sqb[c & 1023], sc1 = sqb[(c + 1) & 1023];
                v0 = 2.f * v0 - sr0 - sc0; v1 = 2.f * v1 - sr0 - sc1;
                v2 = 2.f * v2 - sr8 - sc0; v3 = 2.f * v3 - sr8 - sc1;
            }
            *(float2*)&C[(size_t)r * ldc + c] = make_float2(v0, v1);
            *(float2*)&C[(size_t)(r + 8) * ldc + c] = make_float2(v2, v3);
            if (mode == 1 && bi != bj) {
                C[(size_t)c * ldc + r] = v0;
                C[(size_t)(c + 1) * ldc + r] = v1;
                C[(size_t)c * ldc + r + 8] = v2;
                C[(size_t)(c + 1) * ldc + r + 8] = v3;
            }
        }
}

// ---------------- 128x128x8 FFMA SGEMM (layer 0 only, K=3) -----------------
__global__ void __launch_bounds__(256, 2)
sgemm128(const float* __restrict__ A, int lda, long long sA,
         const float* __restrict__ B, int ldb, long long sB,
         const float* __restrict__ sq,
         float* __restrict__ C, int ldc, long long sC,
         int M, int N, int K, int mode)
{
    int bz = blockIdx.z;
    A += (long long)bz * sA;
    B += (long long)bz * sB;
    C += (long long)bz * sC;
    const float* sqb = sq ? (sq + (long long)bz * M) : nullptr;

    int bi, bj;
    if (mode == 1) {
        int nb = N >> 7;
        int p = blockIdx.x;
        bi = 0;
        while (p >= nb - bi) { p -= nb - bi; bi++; }
        bj = bi + p;
    } else { bi = blockIdx.x; bj = blockIdx.y; }
    const int row0 = bi * 128;
    const int col0 = bj * 128;

    __shared__ float As[2][8][132];
    __shared__ float Bs[2][8][132];

    const int tid = threadIdx.x;
    const int lk = tid & 7;
    const int lm = tid >> 3;
    const int tx = tid & 15;
    const int ty = tid >> 4;

    float acc[8][8];
#pragma unroll
    for (int i = 0; i < 8; i++)
#pragma unroll
        for (int j = 0; j < 8; j++) acc[i][j] = 0.f;

    float pa[4], pb[4];
    const int nk = (K + 7) >> 3;

    {
        int k = lk;
        bool ok = (k < K);
#pragma unroll
        for (int j = 0; j < 4; j++) {
            int m = lm + 32 * j;
            pa[j] = ok ? A[(long long)(row0 + m) * lda + k] : 0.f;
            pb[j] = ok ? B[(long long)(col0 + m) * ldb + k] : 0.f;
        }
#pragma unroll
        for (int j = 0; j < 4; j++) {
            As[0][lk][lm + 32 * j] = pa[j];
            Bs[0][lk][lm + 32 * j] = pb[j];
        }
    }
    __syncthreads();

    for (int t = 0; t < nk; t++) {
        int cur = t & 1;
        if (t + 1 < nk) {
            int k = (t + 1) * 8 + lk;
            bool ok = (k < K);
#pragma unroll
            for (int j = 0; j < 4; j++) {
                int m = lm + 32 * j;
                pa[j] = ok ? A[(long long)(row0 + m) * lda + k] : 0.f;
                pb[j] = ok ? B[(long long)(col0 + m) * ldb + k] : 0.f;
            }
        }
#pragma unroll
        for (int kk = 0; kk < 8; kk++) {
            float a[8], b[8];
            *(float4*)&a[0] = *(const float4*)&As[cur][kk][ty * 4];
            *(float4*)&a[4] = *(const float4*)&As[cur][kk][64 + ty * 4];
            *(float4*)&b[0] = *(const float4*)&Bs[cur][kk][tx * 4];
            *(float4*)&b[4] = *(const float4*)&Bs[cur][kk][64 + tx * 4];
#pragma unroll
            for (int i = 0; i < 8; i++)
#pragma unroll
                for (int j = 0; j < 8; j++)
                    acc[i][j] += a[i] * b[j];
        }
        if (t + 1 < nk) {
            int nxt = cur ^ 1;
#pragma unroll
            for (int j = 0; j < 4; j++) {
                As[nxt][lk][lm + 32 * j] = pa[j];
                Bs[nxt][lk][lm + 32 * j] = pb[j];
            }
        }
        __syncthreads();
    }

#pragma unroll
    for (int ih = 0; ih < 2; ih++) {
#pragma unroll
        for (int i = 0; i < 4; i++) {
            int r = row0 + ih * 64 + ty * 4 + i;
            float srow = (mode == 1) ? sqb[r] : 0.f;
#pragma unroll
            for (int jh = 0; jh < 2; jh++) {
                float outv[4];
#pragma unroll
                for (int j = 0; j < 4; j++) {
                    float v = acc[ih * 4 + i][jh * 4 + j];
                    if (mode == 1)
                        v = (2.f * v - srow) - sqb[col0 + jh * 64 + tx * 4 + j];
                    outv[j] = v;
                }
                *(float4*)&C[(long long)r * ldc + col0 + jh * 64 + tx * 4] =
                    *(float4*)&outv[0];
            }
        }
    }

    if (mode == 1 && bi != bj) {
#pragma unroll
        for (int jh = 0; jh < 2; jh++)
#pragma unroll
            for (int j = 0; j < 4; j++) {
                int c = col0 + jh * 64 + tx * 4 + j;
                float sc = sqb[c];
#pragma unroll
                for (int ih = 0; ih < 2; ih++) {
                    int rb = row0 + ih * 64 + ty * 4;
                    float mv[4];
#pragma unroll
                    for (int i = 0; i < 4; i++)
                        mv[i] = (2.f * acc[ih * 4 + i][jh * 4 + j] - sqb[rb + i]) - sc;
                    *(float4*)&C[(long long)c * ldc + rb] = *(float4*)&mv[0];
                }
            }
    }
}

// ---------------- squared norms (layer 0 input x only) -----------------------
__global__ void sq_kernel(const float* __restrict__ H, int lda, int C,
                          float* __restrict__ SQ)
{
    int gwarp = (blockIdx.x * blockDim.x + threadIdx.x) >> 5;
    int lane = threadIdx.x & 31;
    if (gwarp >= 16 * 1024) return;
    const float* h = H + (long long)gwarp * lda;
    float s = 0.f;
    for (int c = lane; c < C; c += 32) { float v = h[c]; s += v * v; }
#pragma unroll
    for (int d = 16; d > 0; d >>= 1) s += __shfl_down_sync(0xffffffffu, s, d);
    if (lane == 0) SQ[gwarp] = s;
}

// ---------------- top-40: radix levels with early brute-force exit ----------
__global__ void __launch_bounds__(256)
topk40_kernel(const float* __restrict__ S, int* __restrict__ IDX)
{
    int row = blockIdx.x;
    const float* s = S + (long long)row * 1024;
    int tid = threadIdx.x;
    int lane = tid & 31, w = tid >> 5;

    unsigned key[4];
    {
        float4 v = ((const float4*)s)[tid];
        key[0] = encf(v.x); key[1] = encf(v.y);
        key[2] = encf(v.z); key[3] = encf(v.w);
    }
    bool cand[4] = {true, true, true, true};

    __shared__ unsigned hist[256];
    __shared__ unsigned cntge[256];
    __shared__ unsigned wsum[8];
    __shared__ int shB;
    __shared__ unsigned shGT;
    __shared__ int outcnt, tiecnt;
    __shared__ unsigned long long tlist[1024];

    unsigned prefix = 0;
    int kneed = 40;
    unsigned lo = 0, hi = 0;
    int kn = 0;
    int fin = 0;

    for (int level = 0; level < 4 && !fin; level++) {
        const int shift = 24 - 8 * level;
        hist[tid] = 0;
        __syncthreads();
#pragma unroll
        for (int j = 0; j < 4; j++)
            if (cand[j]) atomicAdd(&hist[(key[j] >> shift) & 255u], 1u);
        __syncthreads();

        unsigned v = hist[255 - tid];
#pragma unroll
        for (int d = 1; d < 32; d <<= 1) {
            unsigned n = __shfl_up_sync(0xffffffffu, v, d);
            if (lane >= d) v += n;
        }
        if (lane == 31) wsum[w] = v;
        __syncthreads();
        if (tid == 0) {
            unsigned a = 0;
#pragma unroll
            for (int q = 0; q < 8; q++) { unsigned t2 = wsum[q]; wsum[q] = a; a += t2; }
        }
        __syncthreads();
        cntge[255 - tid] = v + wsum[w];
        __syncthreads();

        unsigned geb = cntge[tid];
        unsigned geb1 = (tid == 255) ? 0u : cntge[tid + 1];
        if (geb >= (unsigned)kneed && geb1 < (unsigned)kneed) {
            shB = tid;
            shGT = geb1;
        }
        __syncthreads();
        int B = shB;
        int gt = (int)shGT;
        kn = kneed - gt;
        int hb = (int)hist[B];
        lo = prefix | ((unsigned)B << shift);
        hi = lo + ((shift < 32) ? ((1u << shift) - 1u) : 0u);
        if (hb == kn) {
            fin = 1;
        } else if (hb <= 96 || shift == 0) {
            fin = 2;
        } else {
            prefix = lo;
            kneed = kn;
#pragma unroll
            for (int j = 0; j < 4; j++)
                cand[j] = cand[j] && (((key[j] >> shift) & 255u) == (unsigned)B);
        }
        __syncthreads();
    }

    if (tid == 0) { outcnt = 0; tiecnt = 0; }
    __syncthreads();

    if (fin == 1) {
        unsigned T = lo - 1u;
#pragma unroll
        for (int j = 0; j < 4; j++) {
            if (key[j] > T) {
                int slot = atomicAdd(&outcnt, 1);
                IDX[row * 40 + slot] = tid * 4 + j;
            }
        }
        return;
    }

#pragma unroll
    for (int j = 0; j < 4; j++) {
        int m = tid * 4 + j;
        unsigned k2 = key[j];
        if (k2 > hi) {
            int slot = atomicAdd(&outcnt, 1);
            IDX[row * 40 + slot] = m;
        } else if (k2 >= lo) {
            int t2 = atomicAdd(&tiecnt, 1);
            tlist[t2] = ((unsigned long long)k2 << 32) | (unsigned)(2047 - m);
        }
    }
    __syncthreads();

    int tt = tiecnt;
    for (int p = tid; p < tt; p += 256) {
        unsigned long long me = tlist[p];
        int rk = 0;
        for (int q = 0; q < tt; q++) rk += (tlist[q] > me);
        if (rk < kn) {
            int slot = atomicAdd(&outcnt, 1);
            IDX[row * 40 + slot] = 2047 - (int)(me & 0xFFFFFFFFull);
        }
    }
}

// ---------------- weight transform ------------------------------------------
__global__ void wprep_kernel(const float* __restrict__ W, float* __restrict__ WPQ,
                             int Co, int C)
{
    int i = blockIdx.x * blockDim.x + threadIdx.x;
    if (i >= Co * C) return;
    int o = i / C, c = i % C;
    float wl = W[o * 2 * C + c];
    float wr = W[o * 2 * C + C + c];
    WPQ[o * C + c] = wl;
    WPQ[(Co + o) * C + c] = wr - wl;
}

// ---------------- gather-max + fused sq + fp16-split outputs ----------------
// blockDim = 128; G = 512/Co points per block; thread owns one float4 group.
// write_a: store next-layer input planes ah/al (OFF for layer 3 — Cw=128 would
// overflow d_ah's 1M words; l3 output is only consumed via the cat slice).
__global__ void __launch_bounds__(128)
edge_gathermax(const float* __restrict__ PQ,
               const int* __restrict__ IDX,
               const float* __restrict__ g,
               const float* __restrict__ bb,
               uint32_t* __restrict__ AH, uint32_t* __restrict__ AL,
               uint32_t* __restrict__ CH, uint32_t* __restrict__ CL,
               float* __restrict__ SQ,
               int Co, int cwoff, int write_sq, int write_a)
{
    const float BN_INV = 0.9999950000374997f;
    const int c4n = Co >> 2;
    const int G = 128 / c4n;
    const int pbase = blockIdx.x * G;

    __shared__ int nb[8 * 40];
    for (int i = threadIdx.x; i < G * 40; i += 128)
        nb[i] = IDX[(pbase + i / 40) * 40 + (i % 40)];
    __syncthreads();

    const int p = threadIdx.x / c4n;
    const int o = (threadIdx.x - p * c4n) * 4;
    const int pt = pbase + p;
    const int b = pt >> 10;
    const int ld = 2 * Co;
    const float* base = PQ + (size_t)(b << 10) * ld + o;
    const int* nbp = nb + p * 40;

    float4 mx = make_float4(-CUDART_INF_F, -CUDART_INF_F, -CUDART_INF_F, -CUDART_INF_F);
    float4 mn = make_float4(CUDART_INF_F, CUDART_INF_F, CUDART_INF_F, CUDART_INF_F);
#pragma unroll 8
    for (int k = 0; k < 40; k++) {
        float4 v = *(const float4*)(base + (size_t)nbp[k] * ld);
        mx.x = fmaxf(mx.x, v.x); mn.x = fminf(mn.x, v.x);
        mx.y = fmaxf(mx.y, v.y); mn.y = fminf(mn.y, v.y);
        mx.z = fmaxf(mx.z, v.z); mn.z = fminf(mn.z, v.z);
        mx.w = fmaxf(mx.w, v.w); mn.w = fminf(mn.w, v.w);
    }
    float4 q  = *(const float4*)&PQ[(size_t)pt * ld + Co + o];
    float4 gg = *(const float4*)&g[o];
    float4 bv = *(const float4*)&bb[o];

    float4 y;
    y.x = (gg.x >= 0.f ? mx.x : mn.x) + q.x;
    y.y = (gg.y >= 0.f ? mx.y : mn.y) + q.y;
    y.z = (gg.z >= 0.f ? mx.z : mn.z) + q.z;
    y.w = (gg.w >= 0.f ? mx.w : mn.w) + q.w;
    y.x = gg.x * (y.x * BN_INV) + bv.x;
    y.y = gg.y * (y.y * BN_INV) + bv.y;
    y.z = gg.z * (y.z * BN_INV) + bv.z;
    y.w = gg.w * (y.w * BN_INV) + bv.w;
    y.x = y.x > 0.f ? y.x : 0.2f * y.x;
    y.y = y.y > 0.f ? y.y : 0.2f * y.y;
    y.z = y.z > 0.f ? y.z : 0.2f * y.z;
    y.w = y.w > 0.f ? y.w : 0.2f * y.w;

    uint2 h, l;
    hsplit2(y.x, y.y, h.x, l.x);
    hsplit2(y.z, y.w, h.y, l.y);
    const int ow = o >> 1;
    const int Cw = Co >> 1;
    if (write_a) {
        *(uint2*)&AH[(size_t)pt * Cw + ow] = h;
        *(uint2*)&AL[(size_t)pt * Cw + ow] = l;
    }
    *(uint2*)&CH[(size_t)pt * 256 + cwoff + ow] = h;
    *(uint2*)&CL[(size_t)pt * 256 + cwoff + ow] = l;

    if (write_sq) {
        float s = y.x * y.x + y.y * y.y + y.z * y.z + y.w * y.w;
        for (int off = c4n >> 1; off >= 1; off >>= 1)
            s += __shfl_xor_sync(0xffffffffu, s, off);
        if ((threadIdx.x & (c4n - 1)) == 0) SQ[pt] = s;
    }
}

// ---------------- gmax init / decode ----------------------------------------
__global__ void gmax_init(unsigned* __restrict__ g)
{
    g[blockIdx.x * 1024 + threadIdx.x] = 0u;
}

__global__ void decode_out(const unsigned* __restrict__ g,
                           const float* __restrict__ bf, float* __restrict__ out)
{
    int i = blockIdx.x * 256 + threadIdx.x;
    unsigned e = g[i];
    unsigned u = (e & 0x80000000u) ? (e ^ 0x80000000u) : ~e;
    out[i] = __uint_as_float(u) + bf[i & 1023];
}

// ---------------- launch -----------------------------------------------------
extern "C" void kernel_launch(void* const* d_in, const int* in_sizes, int n_in,
                              void* d_out, int out_size)
{
    (void)in_sizes; (void)n_in; (void)out_size;
    const float* x  = (const float*)d_in[0];
    const float* w[4]  = {(const float*)d_in[1], (const float*)d_in[4],
                          (const float*)d_in[7], (const float*)d_in[10]};
    const float* g[4]  = {(const float*)d_in[2], (const float*)d_in[5],
                          (const float*)d_in[8], (const float*)d_in[11]};
    const float* bb[4] = {(const float*)d_in[3], (const float*)d_in[6],
                          (const float*)d_in[9], (const float*)d_in[12]};
    const float* wf = (const float*)d_in[13];
    const float* bf = (const float*)d_in[14];
    float* out = (float*)d_out;

    float *dist, *sq, *pq, *wpq; int* idx; unsigned* gm;
    uint32_t *ah, *al, *wh, *wl, *fh, *fl, *chp, *clp;
    cudaGetSymbolAddress((void**)&dist, d_dist);
    cudaGetSymbolAddress((void**)&sq,   d_sq);
    cudaGetSymbolAddress((void**)&idx,  d_idx);
    cudaGetSymbolAddress((void**)&pq,   d_pq);
    cudaGetSymbolAddress((void**)&wpq,  d_wpq);
    cudaGetSymbolAddress((void**)&gm,   d_gmax);
    cudaGetSymbolAddress((void**)&ah,   d_ah);
    cudaGetSymbolAddress((void**)&al,   d_al);
    cudaGetSymbolAddress((void**)&wh,   d_wh);
    cudaGetSymbolAddress((void**)&wl,   d_wl);
    cudaGetSymbolAddress((void**)&fh,   d_fh);
    cudaGetSymbolAddress((void**)&fl,   d_fl);
    cudaGetSymbolAddress((void**)&chp,  d_ch);
    cudaGetSymbolAddress((void**)&clp,  d_cl);

    cudaFuncSetAttribute(hgemm, cudaFuncAttributeMaxDynamicSharedMemorySize,
                         HSMEM);

    const int Cs[4]    = {3, 64, 64, 128};
    const int Cos[4]   = {64, 64, 128, 256};
    const int offs[4]  = {0, 64, 128, 256};
    const int woff[4]  = {0, 1024, 9216, 25600};
    const int woffw[4] = {0, 512, 4608, 12800};

    // layer 0 (K=3: FFMA path)
    gmax_init<<<16, 1024>>>(gm);
    sq_kernel<<<2048, 256>>>(x, 3, 3, sq);
    sgemm128<<<dim3(36, 1, 16), 256>>>(
        x, 3, 1024LL * 3, x, 3, 1024LL * 3, sq,
        dist, 1024, 1024LL * 1024, 1024, 1024, 3, 1);
    topk40_kernel<<<16384, 256>>>(dist, idx);
    for (int l = 0; l < 4; l++)
        wprep_kernel<<<(Cos[l] * Cs[l] + 255) / 256, 256>>>(w[l], wpq + woff[l],
                                                            Cos[l], Cs[l]);
    cvt1d_h<<<(92160 / 4 + 255) / 256, 256>>>(wpq, wh, wl, 92160 / 4);
    cvt1d_h<<<(1024 * 512 / 4 + 255) / 256, 256>>>(wf, fh, fl, 1024 * 512 / 4);
    sgemm128<<<dim3(128, 1, 1), 256>>>(
        x, 3, 0, wpq, 3, 0, nullptr,
        pq, 128, 0, 16384, 128, 3, 0);
    edge_gathermax<<<2048, 128>>>(pq, idx, g[0], bb[0],
                                  ah, al, chp, clp, sq,
                                  64, offs[0] / 2, 1, 1);

    // layers 1-3 on tensor cores (fp16x3); inputs come from gather-written planes
    for (int l = 1; l < 4; l++) {
        int C = Cs[l], Co = Cos[l];
        int Cw = C >> 1;

        hgemm<<<dim3(36, 1, 16), 256, HSMEM>>>(
            ah, al, Cw, 1024LL * Cw, nullptr, nullptr, 0, sq,
            dist, 1024, 1024LL * 1024, 1024, C, 1, nullptr);
        topk40_kernel<<<16384, 256>>>(dist, idx);
        hgemm<<<dim3(128, (2 * Co) / 128, 1), 256, HSMEM>>>(
            ah, al, Cw, 0, wh + woffw[l], wl + woffw[l], Cw, nullptr,
            pq, 2 * Co, 0, 2 * Co, C, 0, nullptr);
        edge_gathermax<<<16384 * Co / 512, 128>>>(pq, idx, g[l], bb[l],
                                                  ah, al, chp, clp, sq,
                                                  Co, offs[l] / 2,
                                                  (l < 3) ? 1 : 0,
                                                  (l < 3) ? 1 : 0);
    }

    // final linear 512 -> 1024 (fp16x3, fused max over N)
    hgemm<<<dim3(128, 8, 1), 256, HSMEM>>>(
        chp, clp, 256, 0, fh, fl, 256, nullptr,
        dist, 0, 0, 1024, 512, 2, gm);
    decode_out<<<64, 256>>>(gm, bf, out);
}